// round 8
// baseline (speedup 1.0000x reference)
#include <cuda_runtime.h>
#include <cuda_bf16.h>
#include <math.h>

#define BSZ 2
#define TT 2048
#define DD 1024
#define NST 16
#define RK 64
#define BT (BSZ*TT)          // 4096
#define NC 128               // chunks
#define CH (TT/NC)           // 16 steps per chunk
#define PCOLS 96             // 16 B + 16 C + 64 R
#define KSPLIT 16
#define LOG2E 1.44269504f

#define NX4  (BT*DD/4)       // 1048576 float4 of x
#define NW4  (PCOLS*DD/4)    // 24576  float4 of [WB;WC;Wdt1]
#define NW24 (DD*RK/4)       // 16384  float4 of W2
#define NSPLIT4 (NX4 + NW4 + NW24)

__device__ __forceinline__ float ex2(float v) {
    float r; asm("ex2.approx.f32 %0, %1;" : "=f"(r) : "f"(v)); return r;
}

// ---------------- scratch (static device memory; no allocs allowed) --------
__device__ float g_part[KSPLIT * BT * PCOLS]; // split-K partials
__device__ float g_proj[BT * PCOLS];          // col 0-15 = B_t, 16-31 = C_t, 32-95 = R
__device__ float g_dt[BT * DD];               // softplus(dt_raw)
__device__ float g_P[BSZ * NC * DD * NST];    // per-chunk product of a_t
__device__ float g_H[BSZ * NC * DD * NST];    // chunk-local final h -> becomes init h
__device__ __nv_bfloat16 g_xhi[BT * DD];      // bf16 split of x
__device__ __nv_bfloat16 g_xlo[BT * DD];
__device__ __nv_bfloat16 g_whi[PCOLS * DD];   // bf16 split of [WB;WC;Wdt1]
__device__ __nv_bfloat16 g_wlo[PCOLS * DD];
__device__ __nv_bfloat16 g_w2hi[DD * RK];     // bf16 split of W2
__device__ __nv_bfloat16 g_w2lo[DD * RK];
__device__ __nv_bfloat16 g_rhi[BT * RK];      // bf16 split of R (proj cols 32-95)
__device__ __nv_bfloat16 g_rlo[BT * RK];

// split one float4 into two packed bf16x4 (hi, lo)
__device__ __forceinline__ void split4(float4 v, uint2& hw, uint2& lw) {
    float f[4] = {v.x, v.y, v.z, v.w};
    unsigned h[2], l[2];
#pragma unroll
    for (int k = 0; k < 2; k++) {
        __nv_bfloat16 h0 = __float2bfloat16(f[2 * k]);
        __nv_bfloat16 h1 = __float2bfloat16(f[2 * k + 1]);
        __nv_bfloat16 l0 = __float2bfloat16(f[2 * k] - __bfloat162float(h0));
        __nv_bfloat16 l1 = __float2bfloat16(f[2 * k + 1] - __bfloat162float(h1));
        h[k] = (unsigned)__bfloat16_as_ushort(h0) | ((unsigned)__bfloat16_as_ushort(h1) << 16);
        l[k] = (unsigned)__bfloat16_as_ushort(l0) | ((unsigned)__bfloat16_as_ushort(l1) << 16);
    }
    hw = make_uint2(h[0], h[1]);
    lw = make_uint2(l[0], l[1]);
}

// ---------------- kernel 0: ALL fp32 -> bf16 hi/lo splits in one launch ----
__global__ __launch_bounds__(256) void split_all(const float* __restrict__ x,
                                                 const float* __restrict__ WB,
                                                 const float* __restrict__ WC,
                                                 const float* __restrict__ Wdt1,
                                                 const float* __restrict__ W2) {
    int i = blockIdx.x * 256 + threadIdx.x;
    if (i >= NSPLIT4) return;
    float4 v;
    uint2 hw, lw;
    if (i < NX4) {
        v = reinterpret_cast<const float4*>(x)[i];
        split4(v, hw, lw);
        reinterpret_cast<uint2*>(g_xhi)[i] = hw;
        reinterpret_cast<uint2*>(g_xlo)[i] = lw;
    } else if (i < NX4 + NW4) {
        int off = i - NX4;                    // float4 within 96xDD
        int foff = off * 4;
        int n = foff >> 10, k = foff & 1023;  // DD = 1024
        const float* src = (n < 16) ? (WB + (size_t)n * DD)
                          : (n < 32) ? (WC + (size_t)(n - 16) * DD)
                                     : (Wdt1 + (size_t)(n - 32) * DD);
        v = *reinterpret_cast<const float4*>(src + k);
        split4(v, hw, lw);
        reinterpret_cast<uint2*>(g_whi)[off] = hw;
        reinterpret_cast<uint2*>(g_wlo)[off] = lw;
    } else {
        int off = i - NX4 - NW4;
        v = reinterpret_cast<const float4*>(W2)[off];
        split4(v, hw, lw);
        reinterpret_cast<uint2*>(g_w2hi)[off] = hw;
        reinterpret_cast<uint2*>(g_w2lo)[off] = lw;
    }
}

// ---------------- kernel 1: proj GEMM via tensor cores ---------------------
__device__ __forceinline__ void mma_bf16(float* d, const unsigned* a,
                                         unsigned b0, unsigned b1) {
    asm("mma.sync.aligned.m16n8k16.row.col.f32.bf16.bf16.f32 "
        "{%0,%1,%2,%3}, {%4,%5,%6,%7}, {%8,%9}, {%0,%1,%2,%3};"
        : "+f"(d[0]), "+f"(d[1]), "+f"(d[2]), "+f"(d[3])
        : "r"(a[0]), "r"(a[1]), "r"(a[2]), "r"(a[3]), "r"(b0), "r"(b1));
}

__global__ __launch_bounds__(256) void proj_mma() {
    __shared__ __nv_bfloat16 As[128][40];
    __shared__ __nv_bfloat16 Bs[96][40];
    const int tid = threadIdx.x;
    const int lane = tid & 31, wid = tid >> 5;
    const int warpM = wid & 3;
    const int warpN = wid >> 2;
    const int row0 = blockIdx.x * 128;
    const int kb = blockIdx.y * (DD / KSPLIT);

    float acc[2][6][4];
#pragma unroll
    for (int mt = 0; mt < 2; mt++)
#pragma unroll
        for (int nt = 0; nt < 6; nt++)
#pragma unroll
            for (int q = 0; q < 4; q++) acc[mt][nt][q] = 0.0f;

#pragma unroll 1
    for (int seg = 0; seg < 3; seg++) {
        const __nv_bfloat16* Ap = (seg < 2) ? g_xhi : g_xlo;
        const __nv_bfloat16* Bp = (seg == 1) ? g_wlo : g_whi;
#pragma unroll 1
        for (int kt = 0; kt < 2; kt++) {
            const int kcur = kb + kt * 32;
#pragma unroll
            for (int i = 0; i < 4; i++) {
                int lin = tid + i * 256;
                int r = lin >> 3, q = lin & 7;
                *reinterpret_cast<uint2*>(&As[r][q * 4]) =
                    *reinterpret_cast<const uint2*>(Ap + (size_t)(row0 + r) * DD + kcur + q * 4);
            }
#pragma unroll
            for (int i = 0; i < 3; i++) {
                int lin = tid + i * 256;
                if (lin < 768) {
                    int n = lin >> 3, q = lin & 7;
                    *reinterpret_cast<uint2*>(&Bs[n][q * 4]) =
                        *reinterpret_cast<const uint2*>(Bp + (size_t)n * DD + kcur + q * 4);
                }
            }
            __syncthreads();
#pragma unroll
            for (int k16 = 0; k16 < 32; k16 += 16) {
                const int ccol = k16 + (lane & 3) * 2;
                unsigned a[2][4];
#pragma unroll
                for (int mt = 0; mt < 2; mt++) {
                    int r = warpM * 32 + mt * 16 + (lane >> 2);
                    a[mt][0] = *reinterpret_cast<const unsigned*>(&As[r][ccol]);
                    a[mt][1] = *reinterpret_cast<const unsigned*>(&As[r + 8][ccol]);
                    a[mt][2] = *reinterpret_cast<const unsigned*>(&As[r][ccol + 8]);
                    a[mt][3] = *reinterpret_cast<const unsigned*>(&As[r + 8][ccol + 8]);
                }
#pragma unroll
                for (int nt = 0; nt < 6; nt++) {
                    int n = warpN * 48 + nt * 8 + (lane >> 2);
                    unsigned b0 = *reinterpret_cast<const unsigned*>(&Bs[n][ccol]);
                    unsigned b1 = *reinterpret_cast<const unsigned*>(&Bs[n][ccol + 8]);
                    mma_bf16(acc[0][nt], a[0], b0, b1);
                    mma_bf16(acc[1][nt], a[1], b0, b1);
                }
            }
            __syncthreads();
        }
    }

    float* outp = g_part + (size_t)blockIdx.y * BT * PCOLS;
#pragma unroll
    for (int mt = 0; mt < 2; mt++)
#pragma unroll
        for (int nt = 0; nt < 6; nt++) {
            int r = row0 + warpM * 32 + mt * 16 + (lane >> 2);
            int c = warpN * 48 + nt * 8 + (lane & 3) * 2;
            float2 v0 = {acc[mt][nt][0], acc[mt][nt][1]};
            float2 v1 = {acc[mt][nt][2], acc[mt][nt][3]};
            *reinterpret_cast<float2*>(&outp[(size_t)r * PCOLS + c]) = v0;
            *reinterpret_cast<float2*>(&outp[(size_t)(r + 8) * PCOLS + c]) = v1;
        }
}

// ---------------- kernel 1b: reduce split-K partials + emit bf16 R ---------
__global__ __launch_bounds__(256) void reduce_proj() {
    int i = blockIdx.x * 256 + threadIdx.x;     // float4 index into [row][96]
    if (i < BT * PCOLS / 4) {
        float4 s = {0.f, 0.f, 0.f, 0.f};
#pragma unroll
        for (int k = 0; k < KSPLIT; k++) {
            float4 v = reinterpret_cast<const float4*>(g_part)[(size_t)k * (BT * PCOLS / 4) + i];
            s.x += v.x; s.y += v.y; s.z += v.z; s.w += v.w;
        }
        reinterpret_cast<float4*>(g_proj)[i] = s;
        int col4 = i % (PCOLS / 4);             // 0..23
        if (col4 >= 8) {                        // R columns (32..95)
            int row = i / (PCOLS / 4);
            int rc = col4 * 4 - 32;             // 0..60
            uint2 hw, lw;
            split4(s, hw, lw);
            reinterpret_cast<uint2*>(g_rhi)[(size_t)row * (RK / 4) + (rc >> 2)] = hw;
            reinterpret_cast<uint2*>(g_rlo)[(size_t)row * (RK / 4) + (rc >> 2)] = lw;
        }
    }
}

// ---------------- kernel 2: dt GEMM via tensor cores + softplus ------------
// C[4096x1024] = R[4096x64] @ W2^T[64x1024], bf16 2-term split (K=3*64).
// grid (BT/128, DD/64), block 256 (8 warps): warp = 32m x 32n.
__global__ __launch_bounds__(256) void dt_mma(const float* __restrict__ bdt) {
    __shared__ __nv_bfloat16 As[128][72];
    __shared__ __nv_bfloat16 Bs[64][72];
    const int tid = threadIdx.x;
    const int lane = tid & 31, wid = tid >> 5;
    const int warpM = wid & 3;                  // 4 x 32 rows
    const int warpN = wid >> 2;                 // 2 x 32 cols
    const int row0 = blockIdx.x * 128;
    const int col0 = blockIdx.y * 64;

    float acc[2][4][4];
#pragma unroll
    for (int mt = 0; mt < 2; mt++)
#pragma unroll
        for (int nt = 0; nt < 4; nt++)
#pragma unroll
            for (int q = 0; q < 4; q++) acc[mt][nt][q] = 0.0f;

#pragma unroll 1
    for (int seg = 0; seg < 3; seg++) {
        const __nv_bfloat16* Ap = (seg < 2) ? g_rhi : g_rlo;
        const __nv_bfloat16* Bp = (seg == 1) ? g_w2lo : g_w2hi;
#pragma unroll
        for (int i = 0; i < 8; i++) {           // A: 128 x 64 bf16 = 2048 uint2
            int lin = tid + i * 256;
            int r = lin >> 4, q = lin & 15;
            *reinterpret_cast<uint2*>(&As[r][q * 4]) =
                *reinterpret_cast<const uint2*>(Ap + (size_t)(row0 + r) * RK + q * 4);
        }
#pragma unroll
        for (int i = 0; i < 4; i++) {           // B: 64 x 64 bf16 = 1024 uint2
            int lin = tid + i * 256;
            int n = lin >> 4, q = lin & 15;
            *reinterpret_cast<uint2*>(&Bs[n][q * 4]) =
                *reinterpret_cast<const uint2*>(Bp + (size_t)(col0 + n) * RK + q * 4);
        }
        __syncthreads();
#pragma unroll
        for (int k16 = 0; k16 < 64; k16 += 16) {
            const int ccol = k16 + (lane & 3) * 2;
            unsigned a[2][4];
#pragma unroll
            for (int mt = 0; mt < 2; mt++) {
                int r = warpM * 32 + mt * 16 + (lane >> 2);
                a[mt][0] = *reinterpret_cast<const unsigned*>(&As[r][ccol]);
                a[mt][1] = *reinterpret_cast<const unsigned*>(&As[r + 8][ccol]);
                a[mt][2] = *reinterpret_cast<const unsigned*>(&As[r][ccol + 8]);
                a[mt][3] = *reinterpret_cast<const unsigned*>(&As[r + 8][ccol + 8]);
            }
#pragma unroll
            for (int nt = 0; nt < 4; nt++) {
                int n = warpN * 32 + nt * 8 + (lane >> 2);
                unsigned b0 = *reinterpret_cast<const unsigned*>(&Bs[n][ccol]);
                unsigned b1 = *reinterpret_cast<const unsigned*>(&Bs[n][ccol + 8]);
                mma_bf16(acc[0][nt], a[0], b0, b1);
                mma_bf16(acc[1][nt], a[1], b0, b1);
            }
        }
        __syncthreads();
    }

#pragma unroll
    for (int mt = 0; mt < 2; mt++)
#pragma unroll
        for (int nt = 0; nt < 4; nt++) {
            int r = row0 + warpM * 32 + mt * 16 + (lane >> 2);
            int c = col0 + warpN * 32 + nt * 8 + (lane & 3) * 2;
            float b0 = bdt[c], b1 = bdt[c + 1];
            float v0 = acc[mt][nt][0] + b0;
            float v1 = acc[mt][nt][1] + b1;
            float v2 = acc[mt][nt][2] + b0;
            float v3 = acc[mt][nt][3] + b1;
            float2 r0 = {(v0 > 20.0f) ? v0 : log1pf(__expf(v0)),
                         (v1 > 20.0f) ? v1 : log1pf(__expf(v1))};
            float2 r1 = {(v2 > 20.0f) ? v2 : log1pf(__expf(v2)),
                         (v3 > 20.0f) ? v3 : log1pf(__expf(v3))};
            *reinterpret_cast<float2*>(&g_dt[(size_t)r * DD + c]) = r0;
            *reinterpret_cast<float2*>(&g_dt[(size_t)(r + 8) * DD + c]) = r1;
        }
}

// ---------------- kernel 3: pass 1 — per-chunk local scan ------------------
__global__ __launch_bounds__(256, 6) void scan_pass1(const float* __restrict__ x,
                                                     const float* __restrict__ logA) {
    __shared__ float sdt[CH][128];
    __shared__ float sx[CH][128];
    __shared__ float Bv[CH * NST];
    const int tid = threadIdx.x;
    const int dloc = tid >> 1;
    const int d0 = blockIdx.x * 128;
    const int nb = (tid & 1) * 8;
    const int c = blockIdx.y;
    const int b = blockIdx.z;

    const size_t rowbase = (size_t)(b * TT + c * CH) * DD + d0;
#pragma unroll
    for (int i = 0; i < 2; i++) {
        int lin = tid + i * 256;
        int t = lin >> 5, q = lin & 31;
        *reinterpret_cast<float4*>(&sdt[t][q * 4]) =
            *reinterpret_cast<const float4*>(g_dt + rowbase + (size_t)t * DD + q * 4);
        *reinterpret_cast<float4*>(&sx[t][q * 4]) =
            *reinterpret_cast<const float4*>(x + rowbase + (size_t)t * DD + q * 4);
    }
    {
        int t = tid >> 4, n = tid & 15;
        float A = -__expf(logA[n]);
        Bv[tid] = g_proj[(size_t)(b * TT + c * CH + t) * PCOLS + n] / (A + 1e-8f);
    }

    float An2[8], h[8];
#pragma unroll
    for (int j = 0; j < 8; j++) {
        An2[j] = -__expf(logA[nb + j]) * LOG2E;
        h[j] = 0.0f;
    }
    __syncthreads();

    float sumdt = 0.0f;
#pragma unroll
    for (int t = 0; t < CH; t++) {
        float dtv = sdt[t][dloc];
        float xv = sx[t][dloc];
        sumdt += dtv;
        float4 b0 = *reinterpret_cast<const float4*>(&Bv[t * NST + nb]);
        float4 b1 = *reinterpret_cast<const float4*>(&Bv[t * NST + nb + 4]);
        float bv[8] = {b0.x, b0.y, b0.z, b0.w, b1.x, b1.y, b1.z, b1.w};
#pragma unroll
        for (int j = 0; j < 8; j++) {
            float a = ex2(dtv * An2[j]);
            float g = xv * bv[j];
            h[j] = fmaf(a, h[j] + g, -g);
        }
    }

    const int d = d0 + dloc;
    size_t base = (((size_t)b * NC + c) * DD + d) * NST + nb;
    float4 P0 = {ex2(An2[0] * sumdt), ex2(An2[1] * sumdt),
                 ex2(An2[2] * sumdt), ex2(An2[3] * sumdt)};
    float4 P1 = {ex2(An2[4] * sumdt), ex2(An2[5] * sumdt),
                 ex2(An2[6] * sumdt), ex2(An2[7] * sumdt)};
    *reinterpret_cast<float4*>(g_P + base)     = P0;
    *reinterpret_cast<float4*>(g_P + base + 4) = P1;
    float4 H0 = {h[0], h[1], h[2], h[3]};
    float4 H1 = {h[4], h[5], h[6], h[7]};
    *reinterpret_cast<float4*>(g_H + base)     = H0;
    *reinterpret_cast<float4*>(g_H + base + 4) = H1;
}

// ---------------- kernel 4: combine chunks ---------------------------------
__global__ __launch_bounds__(256) void combine() {
    int idx = blockIdx.x * 256 + threadIdx.x;
    int b = idx / (DD * NST);
    int rem = idx - b * (DD * NST);
    float run = 0.0f;
#pragma unroll 16
    for (int c = 0; c < NC; c++) {
        size_t off = ((size_t)b * NC + c) * (DD * NST) + rem;
        float P = g_P[off];
        float H = g_H[off];
        float nw = fmaf(P, run, H);
        g_H[off] = run;
        run = nw;
    }
}

// ---------------- kernel 5: pass 2 — re-scan with correct init, emit y -----
__global__ __launch_bounds__(256, 6) void scan_pass2(const float* __restrict__ x,
                                                     const float* __restrict__ logA,
                                                     const float* __restrict__ Dskip,
                                                     float* __restrict__ out) {
    __shared__ float sdt[CH][128];
    __shared__ float sx[CH][128];
    __shared__ float sy[CH][128];
    __shared__ float Bv[CH * NST];
    __shared__ float Cs[CH * NST];
    const int tid = threadIdx.x;
    const int dloc = tid >> 1;
    const int d0 = blockIdx.x * 128;
    const int nh = tid & 1;
    const int nb = nh * 8;
    const int c = blockIdx.y;
    const int b = blockIdx.z;

    const size_t rowbase = (size_t)(b * TT + c * CH) * DD + d0;
#pragma unroll
    for (int i = 0; i < 2; i++) {
        int lin = tid + i * 256;
        int t = lin >> 5, q = lin & 31;
        *reinterpret_cast<float4*>(&sdt[t][q * 4]) =
            *reinterpret_cast<const float4*>(g_dt + rowbase + (size_t)t * DD + q * 4);
        *reinterpret_cast<float4*>(&sx[t][q * 4]) =
            *reinterpret_cast<const float4*>(x + rowbase + (size_t)t * DD + q * 4);
    }
    {
        int t = tid >> 4, n = tid & 15;
        float A = -__expf(logA[n]);
        size_t prow = (size_t)(b * TT + c * CH + t) * PCOLS;
        Bv[tid] = g_proj[prow + n] / (A + 1e-8f);
        Cs[tid] = g_proj[prow + 16 + n];
    }

    const int d = d0 + dloc;
    float An2[8], h[8];
    size_t base = (((size_t)b * NC + c) * DD + d) * NST + nb;
    float4 H0 = *reinterpret_cast<const float4*>(g_H + base);
    float4 H1 = *reinterpret_cast<const float4*>(g_H + base + 4);
    h[0] = H0.x; h[1] = H0.y; h[2] = H0.z; h[3] = H0.w;
    h[4] = H1.x; h[5] = H1.y; h[6] = H1.z; h[7] = H1.w;
#pragma unroll
    for (int j = 0; j < 8; j++)
        An2[j] = -__expf(logA[nb + j]) * LOG2E;
    const float dsk = Dskip[d];
    __syncthreads();

#pragma unroll
    for (int t = 0; t < CH; t++) {
        float dtv = sdt[t][dloc];
        float xv = sx[t][dloc];
        float4 b0 = *reinterpret_cast<const float4*>(&Bv[t * NST + nb]);
        float4 b1 = *reinterpret_cast<const float4*>(&Bv[t * NST + nb + 4]);
        float bv[8] = {b0.x, b0.y, b0.z, b0.w, b1.x, b1.y, b1.z, b1.w};
        float4 c0 = *reinterpret_cast<const float4*>(&Cs[t * NST + nb]);
        float4 c1 = *reinterpret_cast<const float4*>(&Cs[t * NST + nb + 4]);
        float cv[8] = {c0.x, c0.y, c0.z, c0.w, c1.x, c1.y, c1.z, c1.w};
        float y = 0.0f;
#pragma unroll
        for (int j = 0; j < 8; j++) {
            float a = ex2(dtv * An2[j]);
            float g = xv * bv[j];
            h[j] = fmaf(a, h[j] + g, -g);
            y = fmaf(h[j], cv[j], y);
        }
        y += __shfl_xor_sync(0xffffffffu, y, 1);
        if (nh == 0) sy[t][dloc] = fmaf(dsk, xv, y);
    }
    __syncthreads();

#pragma unroll
    for (int i = 0; i < 2; i++) {
        int lin = tid + i * 256;
        int t = lin >> 5, q = lin & 31;
        *reinterpret_cast<float4*>(out + rowbase + (size_t)t * DD + q * 4) =
            *reinterpret_cast<const float4*>(&sy[t][q * 4]);
    }
}

// ---------------- launcher -------------------------------------------------
extern "C" void kernel_launch(void* const* d_in, const int* in_sizes, int n_in,
                              void* d_out, int out_size) {
    const float* x    = (const float*)d_in[0];
    const float* WB   = (const float*)d_in[1];
    const float* WC   = (const float*)d_in[2];
    const float* Wdt1 = (const float*)d_in[3];
    const float* Wdt2 = (const float*)d_in[4];
    const float* bdt2 = (const float*)d_in[5];
    const float* logA = (const float*)d_in[6];
    const float* Dsk  = (const float*)d_in[7];
    float* out = (float*)d_out;

    split_all<<<(NSPLIT4 + 255) / 256, 256>>>(x, WB, WC, Wdt1, Wdt2);
    proj_mma<<<dim3(BT / 128, KSPLIT), 256>>>();
    reduce_proj<<<(BT * PCOLS / 4 + 255) / 256, 256>>>();
    dt_mma<<<dim3(BT / 128, DD / 64), 256>>>(bdt2);
    scan_pass1<<<dim3(DD / 128, NC, BSZ), 256>>>(x, logA);
    combine<<<(BSZ * DD * NST) / 256, 256>>>();
    scan_pass2<<<dim3(DD / 128, NC, BSZ), 256>>>(x, logA, Dsk, out);
}

// round 9
// speedup vs baseline: 1.3627x; 1.3627x over previous
#include <cuda_runtime.h>
#include <cuda_bf16.h>
#include <math.h>

#define BSZ 2
#define TT 2048
#define DD 1024
#define NST 16
#define RK 64
#define BT (BSZ*TT)          // 4096
#define NC 128               // chunks
#define CH (TT/NC)           // 16 steps per chunk
#define PCOLS 96             // 16 B + 16 C + 64 R
#define KSPLIT 16
#define LOG2E 1.44269504f

#define NX4  (BT*DD/4)       // 1048576 float4 of x
#define NW4  (PCOLS*DD/4)    // 24576  float4 of [WB;WC;Wdt1]
#define NSPLIT4 (NX4 + NW4)

__device__ __forceinline__ float ex2(float v) {
    float r; asm("ex2.approx.f32 %0, %1;" : "=f"(r) : "f"(v)); return r;
}

// ---------------- scratch (static device memory; no allocs allowed) --------
__device__ float g_part[KSPLIT * BT * PCOLS]; // split-K partials
__device__ float g_proj[BT * PCOLS];          // col 0-15 = B_t, 16-31 = C_t, 32-95 = R
__device__ float g_dt[BT * DD];               // softplus(dt_raw)
__device__ float g_P[BSZ * NC * DD * NST];    // per-chunk product of a_t
__device__ float g_H[BSZ * NC * DD * NST];    // chunk-local final h -> becomes init h
__device__ __nv_bfloat16 g_xhi[BT * DD];      // bf16 split of x
__device__ __nv_bfloat16 g_xlo[BT * DD];
__device__ __nv_bfloat16 g_whi[PCOLS * DD];   // bf16 split of [WB;WC;Wdt1]
__device__ __nv_bfloat16 g_wlo[PCOLS * DD];

// split one float4 into two packed bf16x4 (hi, lo)
__device__ __forceinline__ void split4(float4 v, uint2& hw, uint2& lw) {
    float f[4] = {v.x, v.y, v.z, v.w};
    unsigned h[2], l[2];
#pragma unroll
    for (int k = 0; k < 2; k++) {
        __nv_bfloat16 h0 = __float2bfloat16(f[2 * k]);
        __nv_bfloat16 h1 = __float2bfloat16(f[2 * k + 1]);
        __nv_bfloat16 l0 = __float2bfloat16(f[2 * k] - __bfloat162float(h0));
        __nv_bfloat16 l1 = __float2bfloat16(f[2 * k + 1] - __bfloat162float(h1));
        h[k] = (unsigned)__bfloat16_as_ushort(h0) | ((unsigned)__bfloat16_as_ushort(h1) << 16);
        l[k] = (unsigned)__bfloat16_as_ushort(l0) | ((unsigned)__bfloat16_as_ushort(l1) << 16);
    }
    hw = make_uint2(h[0], h[1]);
    lw = make_uint2(l[0], l[1]);
}

// ---------------- kernel 0: ALL fp32 -> bf16 hi/lo splits in one launch ----
__global__ __launch_bounds__(256) void split_all(const float* __restrict__ x,
                                                 const float* __restrict__ WB,
                                                 const float* __restrict__ WC,
                                                 const float* __restrict__ Wdt1) {
    int i = blockIdx.x * 256 + threadIdx.x;
    if (i >= NSPLIT4) return;
    float4 v;
    uint2 hw, lw;
    if (i < NX4) {
        v = reinterpret_cast<const float4*>(x)[i];
        split4(v, hw, lw);
        reinterpret_cast<uint2*>(g_xhi)[i] = hw;
        reinterpret_cast<uint2*>(g_xlo)[i] = lw;
    } else {
        int off = i - NX4;                    // float4 within 96xDD
        int foff = off * 4;
        int n = foff >> 10, k = foff & 1023;  // DD = 1024
        const float* src = (n < 16) ? (WB + (size_t)n * DD)
                          : (n < 32) ? (WC + (size_t)(n - 16) * DD)
                                     : (Wdt1 + (size_t)(n - 32) * DD);
        v = *reinterpret_cast<const float4*>(src + k);
        split4(v, hw, lw);
        reinterpret_cast<uint2*>(g_whi)[off] = hw;
        reinterpret_cast<uint2*>(g_wlo)[off] = lw;
    }
}

// ---------------- kernel 1: proj GEMM via tensor cores ---------------------
__device__ __forceinline__ void mma_bf16(float* d, const unsigned* a,
                                         unsigned b0, unsigned b1) {
    asm("mma.sync.aligned.m16n8k16.row.col.f32.bf16.bf16.f32 "
        "{%0,%1,%2,%3}, {%4,%5,%6,%7}, {%8,%9}, {%0,%1,%2,%3};"
        : "+f"(d[0]), "+f"(d[1]), "+f"(d[2]), "+f"(d[3])
        : "r"(a[0]), "r"(a[1]), "r"(a[2]), "r"(a[3]), "r"(b0), "r"(b1));
}

__global__ __launch_bounds__(256) void proj_mma() {
    __shared__ __nv_bfloat16 As[128][40];
    __shared__ __nv_bfloat16 Bs[96][40];
    const int tid = threadIdx.x;
    const int lane = tid & 31, wid = tid >> 5;
    const int warpM = wid & 3;
    const int warpN = wid >> 2;
    const int row0 = blockIdx.x * 128;
    const int kb = blockIdx.y * (DD / KSPLIT);

    float acc[2][6][4];
#pragma unroll
    for (int mt = 0; mt < 2; mt++)
#pragma unroll
        for (int nt = 0; nt < 6; nt++)
#pragma unroll
            for (int q = 0; q < 4; q++) acc[mt][nt][q] = 0.0f;

#pragma unroll 1
    for (int seg = 0; seg < 3; seg++) {
        const __nv_bfloat16* Ap = (seg < 2) ? g_xhi : g_xlo;
        const __nv_bfloat16* Bp = (seg == 1) ? g_wlo : g_whi;
#pragma unroll 1
        for (int kt = 0; kt < 2; kt++) {
            const int kcur = kb + kt * 32;
#pragma unroll
            for (int i = 0; i < 4; i++) {
                int lin = tid + i * 256;
                int r = lin >> 3, q = lin & 7;
                *reinterpret_cast<uint2*>(&As[r][q * 4]) =
                    *reinterpret_cast<const uint2*>(Ap + (size_t)(row0 + r) * DD + kcur + q * 4);
            }
#pragma unroll
            for (int i = 0; i < 3; i++) {
                int lin = tid + i * 256;
                if (lin < 768) {
                    int n = lin >> 3, q = lin & 7;
                    *reinterpret_cast<uint2*>(&Bs[n][q * 4]) =
                        *reinterpret_cast<const uint2*>(Bp + (size_t)n * DD + kcur + q * 4);
                }
            }
            __syncthreads();
#pragma unroll
            for (int k16 = 0; k16 < 32; k16 += 16) {
                const int ccol = k16 + (lane & 3) * 2;
                unsigned a[2][4];
#pragma unroll
                for (int mt = 0; mt < 2; mt++) {
                    int r = warpM * 32 + mt * 16 + (lane >> 2);
                    a[mt][0] = *reinterpret_cast<const unsigned*>(&As[r][ccol]);
                    a[mt][1] = *reinterpret_cast<const unsigned*>(&As[r + 8][ccol]);
                    a[mt][2] = *reinterpret_cast<const unsigned*>(&As[r][ccol + 8]);
                    a[mt][3] = *reinterpret_cast<const unsigned*>(&As[r + 8][ccol + 8]);
                }
#pragma unroll
                for (int nt = 0; nt < 6; nt++) {
                    int n = warpN * 48 + nt * 8 + (lane >> 2);
                    unsigned b0 = *reinterpret_cast<const unsigned*>(&Bs[n][ccol]);
                    unsigned b1 = *reinterpret_cast<const unsigned*>(&Bs[n][ccol + 8]);
                    mma_bf16(acc[0][nt], a[0], b0, b1);
                    mma_bf16(acc[1][nt], a[1], b0, b1);
                }
            }
            __syncthreads();
        }
    }

    float* outp = g_part + (size_t)blockIdx.y * BT * PCOLS;
#pragma unroll
    for (int mt = 0; mt < 2; mt++)
#pragma unroll
        for (int nt = 0; nt < 6; nt++) {
            int r = row0 + warpM * 32 + mt * 16 + (lane >> 2);
            int c = warpN * 48 + nt * 8 + (lane & 3) * 2;
            float2 v0 = {acc[mt][nt][0], acc[mt][nt][1]};
            float2 v1 = {acc[mt][nt][2], acc[mt][nt][3]};
            *reinterpret_cast<float2*>(&outp[(size_t)r * PCOLS + c]) = v0;
            *reinterpret_cast<float2*>(&outp[(size_t)(r + 8) * PCOLS + c]) = v1;
        }
}

// ---------------- kernel 1b: reduce split-K partials (float4) --------------
__global__ __launch_bounds__(256) void reduce_proj() {
    int i = blockIdx.x * 256 + threadIdx.x;     // float4 index
    if (i < BT * PCOLS / 4) {
        float4 s = {0.f, 0.f, 0.f, 0.f};
#pragma unroll
        for (int k = 0; k < KSPLIT; k++) {
            float4 v = reinterpret_cast<const float4*>(g_part)[(size_t)k * (BT * PCOLS / 4) + i];
            s.x += v.x; s.y += v.y; s.z += v.z; s.w += v.w;
        }
        reinterpret_cast<float4*>(g_proj)[i] = s;
    }
}

// ---------------- kernel 2: dt GEMM (M=4096, Nout=1024, K=64) + softplus ---
__global__ __launch_bounds__(256) void dt_gemm(const float* __restrict__ W2,
                                               const float* __restrict__ bdt) {
    __shared__ float as[64][68];   // [kk][row]
    __shared__ float ws[64][68];   // [kk][col]
    const int tid = threadIdx.x;
    const int tx = tid & 15, ty = tid >> 4;     // cols tx*4.., rows ty*4..
    const int row0 = blockIdx.x * 64;
    const int col0 = blockIdx.y * 64;

#pragma unroll
    for (int i = 0; i < 4; i++) {               // A: 64 rows x 64 kk
        int lin = tid + i * 256;                // 1024 float4
        int r = lin >> 4, q = lin & 15;
        float4 v = *reinterpret_cast<const float4*>(
            g_proj + (size_t)(row0 + r) * PCOLS + 32 + q * 4);
        as[q * 4 + 0][r] = v.x; as[q * 4 + 1][r] = v.y;
        as[q * 4 + 2][r] = v.z; as[q * 4 + 3][r] = v.w;
    }
#pragma unroll
    for (int i = 0; i < 4; i++) {               // B: 64 cols x 64 kk
        int lin = tid + i * 256;
        int c = lin >> 4, q = lin & 15;
        float4 v = *reinterpret_cast<const float4*>(
            W2 + (size_t)(col0 + c) * RK + q * 4);
        ws[q * 4 + 0][c] = v.x; ws[q * 4 + 1][c] = v.y;
        ws[q * 4 + 2][c] = v.z; ws[q * 4 + 3][c] = v.w;
    }
    __syncthreads();

    float acc[4][4];
#pragma unroll
    for (int i = 0; i < 4; i++)
#pragma unroll
        for (int j = 0; j < 4; j++) acc[i][j] = 0.0f;

#pragma unroll
    for (int kk = 0; kk < 64; kk++) {
        float4 a = *reinterpret_cast<const float4*>(&as[kk][ty * 4]);
        float4 w = *reinterpret_cast<const float4*>(&ws[kk][tx * 4]);
        float av[4] = {a.x, a.y, a.z, a.w};
        float wv[4] = {w.x, w.y, w.z, w.w};
#pragma unroll
        for (int i = 0; i < 4; i++)
#pragma unroll
            for (int j = 0; j < 4; j++) acc[i][j] = fmaf(av[i], wv[j], acc[i][j]);
    }

    float bias[4];
#pragma unroll
    for (int j = 0; j < 4; j++) bias[j] = bdt[col0 + tx * 4 + j];
#pragma unroll
    for (int i = 0; i < 4; i++) {
        float4 r;
        float* rp = &r.x;
#pragma unroll
        for (int j = 0; j < 4; j++) {
            float v = acc[i][j] + bias[j];
            rp[j] = (v > 20.0f) ? v : log1pf(__expf(v));
        }
        *reinterpret_cast<float4*>(
            g_dt + (size_t)(row0 + ty * 4 + i) * DD + col0 + tx * 4) = r;
    }
}

// ---------------- kernel 3: pass 1 — per-chunk local scan ------------------
__global__ __launch_bounds__(256, 6) void scan_pass1(const float* __restrict__ x,
                                                     const float* __restrict__ logA) {
    __shared__ float sdt[CH][128];
    __shared__ float sx[CH][128];
    __shared__ float Bv[CH * NST];
    const int tid = threadIdx.x;
    const int dloc = tid >> 1;
    const int d0 = blockIdx.x * 128;
    const int nb = (tid & 1) * 8;
    const int c = blockIdx.y;
    const int b = blockIdx.z;

    const size_t rowbase = (size_t)(b * TT + c * CH) * DD + d0;
#pragma unroll
    for (int i = 0; i < 2; i++) {
        int lin = tid + i * 256;
        int t = lin >> 5, q = lin & 31;
        *reinterpret_cast<float4*>(&sdt[t][q * 4]) =
            *reinterpret_cast<const float4*>(g_dt + rowbase + (size_t)t * DD + q * 4);
        *reinterpret_cast<float4*>(&sx[t][q * 4]) =
            *reinterpret_cast<const float4*>(x + rowbase + (size_t)t * DD + q * 4);
    }
    {
        int t = tid >> 4, n = tid & 15;
        float A = -__expf(logA[n]);
        Bv[tid] = g_proj[(size_t)(b * TT + c * CH + t) * PCOLS + n] / (A + 1e-8f);
    }

    float An2[8], h[8];
#pragma unroll
    for (int j = 0; j < 8; j++) {
        An2[j] = -__expf(logA[nb + j]) * LOG2E;
        h[j] = 0.0f;
    }
    __syncthreads();

    float sumdt = 0.0f;
#pragma unroll
    for (int t = 0; t < CH; t++) {
        float dtv = sdt[t][dloc];
        float xv = sx[t][dloc];
        sumdt += dtv;
        float4 b0 = *reinterpret_cast<const float4*>(&Bv[t * NST + nb]);
        float4 b1 = *reinterpret_cast<const float4*>(&Bv[t * NST + nb + 4]);
        float bv[8] = {b0.x, b0.y, b0.z, b0.w, b1.x, b1.y, b1.z, b1.w};
#pragma unroll
        for (int j = 0; j < 8; j++) {
            float a = ex2(dtv * An2[j]);
            float g = xv * bv[j];
            h[j] = fmaf(a, h[j] + g, -g);
        }
    }

    const int d = d0 + dloc;
    size_t base = (((size_t)b * NC + c) * DD + d) * NST + nb;
    float4 P0 = {ex2(An2[0] * sumdt), ex2(An2[1] * sumdt),
                 ex2(An2[2] * sumdt), ex2(An2[3] * sumdt)};
    float4 P1 = {ex2(An2[4] * sumdt), ex2(An2[5] * sumdt),
                 ex2(An2[6] * sumdt), ex2(An2[7] * sumdt)};
    *reinterpret_cast<float4*>(g_P + base)     = P0;
    *reinterpret_cast<float4*>(g_P + base + 4) = P1;
    float4 H0 = {h[0], h[1], h[2], h[3]};
    float4 H1 = {h[4], h[5], h[6], h[7]};
    *reinterpret_cast<float4*>(g_H + base)     = H0;
    *reinterpret_cast<float4*>(g_H + base + 4) = H1;
}

// ---------------- kernel 4: combine chunks ---------------------------------
__global__ __launch_bounds__(256) void combine() {
    int idx = blockIdx.x * 256 + threadIdx.x;
    int b = idx / (DD * NST);
    int rem = idx - b * (DD * NST);
    float run = 0.0f;
#pragma unroll 16
    for (int c = 0; c < NC; c++) {
        size_t off = ((size_t)b * NC + c) * (DD * NST) + rem;
        float P = g_P[off];
        float H = g_H[off];
        float nw = fmaf(P, run, H);
        g_H[off] = run;
        run = nw;
    }
}

// ---------------- kernel 5: pass 2 — re-scan with correct init, emit y -----
__global__ __launch_bounds__(256, 6) void scan_pass2(const float* __restrict__ x,
                                                     const float* __restrict__ logA,
                                                     const float* __restrict__ Dskip,
                                                     float* __restrict__ out) {
    __shared__ float sdt[CH][128];
    __shared__ float sx[CH][128];
    __shared__ float sy[CH][128];
    __shared__ float Bv[CH * NST];
    __shared__ float Cs[CH * NST];
    const int tid = threadIdx.x;
    const int dloc = tid >> 1;
    const int d0 = blockIdx.x * 128;
    const int nh = tid & 1;
    const int nb = nh * 8;
    const int c = blockIdx.y;
    const int b = blockIdx.z;

    const size_t rowbase = (size_t)(b * TT + c * CH) * DD + d0;
#pragma unroll
    for (int i = 0; i < 2; i++) {
        int lin = tid + i * 256;
        int t = lin >> 5, q = lin & 31;
        *reinterpret_cast<float4*>(&sdt[t][q * 4]) =
            *reinterpret_cast<const float4*>(g_dt + rowbase + (size_t)t * DD + q * 4);
        *reinterpret_cast<float4*>(&sx[t][q * 4]) =
            *reinterpret_cast<const float4*>(x + rowbase + (size_t)t * DD + q * 4);
    }
    {
        int t = tid >> 4, n = tid & 15;
        float A = -__expf(logA[n]);
        size_t prow = (size_t)(b * TT + c * CH + t) * PCOLS;
        Bv[tid] = g_proj[prow + n] / (A + 1e-8f);
        Cs[tid] = g_proj[prow + 16 + n];
    }

    const int d = d0 + dloc;
    float An2[8], h[8];
    size_t base = (((size_t)b * NC + c) * DD + d) * NST + nb;
    float4 H0 = *reinterpret_cast<const float4*>(g_H + base);
    float4 H1 = *reinterpret_cast<const float4*>(g_H + base + 4);
    h[0] = H0.x; h[1] = H0.y; h[2] = H0.z; h[3] = H0.w;
    h[4] = H1.x; h[5] = H1.y; h[6] = H1.z; h[7] = H1.w;
#pragma unroll
    for (int j = 0; j < 8; j++)
        An2[j] = -__expf(logA[nb + j]) * LOG2E;
    const float dsk = Dskip[d];
    __syncthreads();

#pragma unroll
    for (int t = 0; t < CH; t++) {
        float dtv = sdt[t][dloc];
        float xv = sx[t][dloc];
        float4 b0 = *reinterpret_cast<const float4*>(&Bv[t * NST + nb]);
        float4 b1 = *reinterpret_cast<const float4*>(&Bv[t * NST + nb + 4]);
        float bv[8] = {b0.x, b0.y, b0.z, b0.w, b1.x, b1.y, b1.z, b1.w};
        float4 c0 = *reinterpret_cast<const float4*>(&Cs[t * NST + nb]);
        float4 c1 = *reinterpret_cast<const float4*>(&Cs[t * NST + nb + 4]);
        float cv[8] = {c0.x, c0.y, c0.z, c0.w, c1.x, c1.y, c1.z, c1.w};
        float y = 0.0f;
#pragma unroll
        for (int j = 0; j < 8; j++) {
            float a = ex2(dtv * An2[j]);
            float g = xv * bv[j];
            h[j] = fmaf(a, h[j] + g, -g);
            y = fmaf(h[j], cv[j], y);
        }
        y += __shfl_xor_sync(0xffffffffu, y, 1);
        if (nh == 0) sy[t][dloc] = fmaf(dsk, xv, y);
    }
    __syncthreads();

#pragma unroll
    for (int i = 0; i < 2; i++) {
        int lin = tid + i * 256;
        int t = lin >> 5, q = lin & 31;
        *reinterpret_cast<float4*>(out + rowbase + (size_t)t * DD + q * 4) =
            *reinterpret_cast<const float4*>(&sy[t][q * 4]);
    }
}

// ---------------- launcher -------------------------------------------------
extern "C" void kernel_launch(void* const* d_in, const int* in_sizes, int n_in,
                              void* d_out, int out_size) {
    const float* x    = (const float*)d_in[0];
    const float* WB   = (const float*)d_in[1];
    const float* WC   = (const float*)d_in[2];
    const float* Wdt1 = (const float*)d_in[3];
    const float* Wdt2 = (const float*)d_in[4];
    const float* bdt2 = (const float*)d_in[5];
    const float* logA = (const float*)d_in[6];
    const float* Dsk  = (const float*)d_in[7];
    float* out = (float*)d_out;

    split_all<<<(NSPLIT4 + 255) / 256, 256>>>(x, WB, WC, Wdt1);
    proj_mma<<<dim3(BT / 128, KSPLIT), 256>>>();
    reduce_proj<<<(BT * PCOLS / 4 + 255) / 256, 256>>>();
    dt_gemm<<<dim3(BT / 64, DD / 64), 256>>>(Wdt2, bdt2);
    scan_pass1<<<dim3(DD / 128, NC, BSZ), 256>>>(x, logA);
    combine<<<(BSZ * DD * NST) / 256, 256>>>();
    scan_pass2<<<dim3(DD / 128, NC, BSZ), 256>>>(x, logA, Dsk, out);
}

// round 10
// speedup vs baseline: 1.4279x; 1.0479x over previous
#include <cuda_runtime.h>
#include <cuda_bf16.h>
#include <math.h>

#define BSZ 2
#define TT 2048
#define DD 1024
#define NST 16
#define RK 64
#define BT (BSZ*TT)          // 4096
#define NC 128               // chunks
#define CH (TT/NC)           // 16 steps per chunk
#define PCOLS 96             // 16 B + 16 C + 64 R
#define KSPLIT 16
#define LOG2E 1.44269504f

__device__ __forceinline__ float ex2(float v) {
    float r; asm("ex2.approx.f32 %0, %1;" : "=f"(r) : "f"(v)); return r;
}

// ---------------- scratch (static device memory; no allocs allowed) --------
__device__ float g_part[KSPLIT * BT * PCOLS]; // split-K partials
__device__ float g_proj[BT * PCOLS];          // col 0-15 = B_t, 16-31 = C_t, 32-95 = R
__device__ float g_dt[BT * DD];               // softplus(dt_raw)
__device__ float g_P[BSZ * NC * DD * NST];    // per-chunk product of a_t
__device__ float g_H[BSZ * NC * DD * NST];    // chunk-local final h -> becomes init h

// split one float4 into two packed bf16x4 (hi, lo)
__device__ __forceinline__ void split4(float4 v, uint2& hw, uint2& lw) {
    float f[4] = {v.x, v.y, v.z, v.w};
    unsigned h[2], l[2];
#pragma unroll
    for (int k = 0; k < 2; k++) {
        __nv_bfloat16 h0 = __float2bfloat16(f[2 * k]);
        __nv_bfloat16 h1 = __float2bfloat16(f[2 * k + 1]);
        __nv_bfloat16 l0 = __float2bfloat16(f[2 * k] - __bfloat162float(h0));
        __nv_bfloat16 l1 = __float2bfloat16(f[2 * k + 1] - __bfloat162float(h1));
        h[k] = (unsigned)__bfloat16_as_ushort(h0) | ((unsigned)__bfloat16_as_ushort(h1) << 16);
        l[k] = (unsigned)__bfloat16_as_ushort(l0) | ((unsigned)__bfloat16_as_ushort(l1) << 16);
    }
    hw = make_uint2(h[0], h[1]);
    lw = make_uint2(l[0], l[1]);
}

// ---------------- kernel 1: proj GEMM via tensor cores ---------------------
// In-kernel fp32->bf16 hi/lo split while staging tiles; 2-term compensation
// (hi*hi + hi*lo + lo*hi terms) over 3 segments from RESIDENT smem.
__device__ __forceinline__ void mma_bf16(float* d, const unsigned* a,
                                         unsigned b0, unsigned b1) {
    asm("mma.sync.aligned.m16n8k16.row.col.f32.bf16.bf16.f32 "
        "{%0,%1,%2,%3}, {%4,%5,%6,%7}, {%8,%9}, {%0,%1,%2,%3};"
        : "+f"(d[0]), "+f"(d[1]), "+f"(d[2]), "+f"(d[3])
        : "r"(a[0]), "r"(a[1]), "r"(a[2]), "r"(a[3]), "r"(b0), "r"(b1));
}

__global__ __launch_bounds__(256) void proj_mma(const float* __restrict__ x,
                                                const float* __restrict__ WB,
                                                const float* __restrict__ WC,
                                                const float* __restrict__ Wdt1) {
    __shared__ __nv_bfloat16 Ahi[128][40];
    __shared__ __nv_bfloat16 Alo[128][40];
    __shared__ __nv_bfloat16 Bhi[96][40];
    __shared__ __nv_bfloat16 Blo[96][40];
    const int tid = threadIdx.x;
    const int lane = tid & 31, wid = tid >> 5;
    const int warpM = wid & 3;              // 4 x 32 rows
    const int warpN = wid >> 2;             // 2 x 48 cols
    const int row0 = blockIdx.x * 128;
    const int kb = blockIdx.y * (DD / KSPLIT);   // 64 K columns per block

    float acc[2][6][4];
#pragma unroll
    for (int mt = 0; mt < 2; mt++)
#pragma unroll
        for (int nt = 0; nt < 6; nt++)
#pragma unroll
            for (int q = 0; q < 4; q++) acc[mt][nt][q] = 0.0f;

#pragma unroll 1
    for (int kt = 0; kt < 2; kt++) {
        const int kcur = kb + kt * 32;
        // stage x tile 128x32: fp32 -> hi/lo bf16 smem
#pragma unroll
        for (int i = 0; i < 4; i++) {
            int lin = tid + i * 256;            // 1024 float4
            int r = lin >> 3, q = lin & 7;
            float4 v = *reinterpret_cast<const float4*>(
                x + (size_t)(row0 + r) * DD + kcur + q * 4);
            uint2 hw, lw;
            split4(v, hw, lw);
            *reinterpret_cast<uint2*>(&Ahi[r][q * 4]) = hw;
            *reinterpret_cast<uint2*>(&Alo[r][q * 4]) = lw;
        }
        // stage W tile 96x32
#pragma unroll
        for (int i = 0; i < 3; i++) {
            int lin = tid + i * 256;
            if (lin < 768) {
                int n = lin >> 3, q = lin & 7;
                const float* src = (n < 16) ? (WB + (size_t)n * DD)
                                  : (n < 32) ? (WC + (size_t)(n - 16) * DD)
                                             : (Wdt1 + (size_t)(n - 32) * DD);
                float4 v = *reinterpret_cast<const float4*>(src + kcur + q * 4);
                uint2 hw, lw;
                split4(v, hw, lw);
                *reinterpret_cast<uint2*>(&Bhi[n][q * 4]) = hw;
                *reinterpret_cast<uint2*>(&Blo[n][q * 4]) = lw;
            }
        }
        __syncthreads();

#pragma unroll
        for (int seg = 0; seg < 3; seg++) {
            const __nv_bfloat16 (*Asp)[40] = (seg < 2) ? Ahi : Alo;
            const __nv_bfloat16 (*Bsp)[40] = (seg == 1) ? Blo : Bhi;
#pragma unroll
            for (int k16 = 0; k16 < 32; k16 += 16) {
                const int ccol = k16 + (lane & 3) * 2;
                unsigned a[2][4];
#pragma unroll
                for (int mt = 0; mt < 2; mt++) {
                    int r = warpM * 32 + mt * 16 + (lane >> 2);
                    a[mt][0] = *reinterpret_cast<const unsigned*>(&Asp[r][ccol]);
                    a[mt][1] = *reinterpret_cast<const unsigned*>(&Asp[r + 8][ccol]);
                    a[mt][2] = *reinterpret_cast<const unsigned*>(&Asp[r][ccol + 8]);
                    a[mt][3] = *reinterpret_cast<const unsigned*>(&Asp[r + 8][ccol + 8]);
                }
#pragma unroll
                for (int nt = 0; nt < 6; nt++) {
                    int n = warpN * 48 + nt * 8 + (lane >> 2);
                    unsigned b0 = *reinterpret_cast<const unsigned*>(&Bsp[n][ccol]);
                    unsigned b1 = *reinterpret_cast<const unsigned*>(&Bsp[n][ccol + 8]);
                    mma_bf16(acc[0][nt], a[0], b0, b1);
                    mma_bf16(acc[1][nt], a[1], b0, b1);
                }
            }
        }
        __syncthreads();
    }

    float* outp = g_part + (size_t)blockIdx.y * BT * PCOLS;
#pragma unroll
    for (int mt = 0; mt < 2; mt++)
#pragma unroll
        for (int nt = 0; nt < 6; nt++) {
            int r = row0 + warpM * 32 + mt * 16 + (lane >> 2);
            int c = warpN * 48 + nt * 8 + (lane & 3) * 2;
            float2 v0 = {acc[mt][nt][0], acc[mt][nt][1]};
            float2 v1 = {acc[mt][nt][2], acc[mt][nt][3]};
            *reinterpret_cast<float2*>(&outp[(size_t)r * PCOLS + c]) = v0;
            *reinterpret_cast<float2*>(&outp[(size_t)(r + 8) * PCOLS + c]) = v1;
        }
}

// ---------------- kernel 1b: reduce split-K partials (float4) --------------
__global__ __launch_bounds__(256) void reduce_proj() {
    int i = blockIdx.x * 256 + threadIdx.x;     // float4 index
    if (i < BT * PCOLS / 4) {
        float4 s = {0.f, 0.f, 0.f, 0.f};
#pragma unroll
        for (int k = 0; k < KSPLIT; k++) {
            float4 v = reinterpret_cast<const float4*>(g_part)[(size_t)k * (BT * PCOLS / 4) + i];
            s.x += v.x; s.y += v.y; s.z += v.z; s.w += v.w;
        }
        reinterpret_cast<float4*>(g_proj)[i] = s;
    }
}

// ---------------- kernel 2: dt GEMM (M=4096, Nout=1024, K=64) + softplus ---
// tile 128x64, thread tile 8x4, full K in smem. grid (BT/128, DD/64).
__global__ __launch_bounds__(256) void dt_gemm(const float* __restrict__ W2,
                                               const float* __restrict__ bdt) {
    __shared__ float as[64][132];  // [kk][row] (128 rows + pad)
    __shared__ float ws[64][68];   // [kk][col]
    const int tid = threadIdx.x;
    const int tx = tid & 15, ty = tid >> 4;     // cols tx*4.., rows ty*8..
    const int row0 = blockIdx.x * 128;
    const int col0 = blockIdx.y * 64;

#pragma unroll
    for (int i = 0; i < 8; i++) {               // A: 128 rows x 64 kk
        int lin = tid + i * 256;                // 2048 float4
        int r = lin >> 4, q = lin & 15;
        float4 v = *reinterpret_cast<const float4*>(
            g_proj + (size_t)(row0 + r) * PCOLS + 32 + q * 4);
        as[q * 4 + 0][r] = v.x; as[q * 4 + 1][r] = v.y;
        as[q * 4 + 2][r] = v.z; as[q * 4 + 3][r] = v.w;
    }
#pragma unroll
    for (int i = 0; i < 4; i++) {               // B: 64 cols x 64 kk
        int lin = tid + i * 256;
        int c = lin >> 4, q = lin & 15;
        float4 v = *reinterpret_cast<const float4*>(
            W2 + (size_t)(col0 + c) * RK + q * 4);
        ws[q * 4 + 0][c] = v.x; ws[q * 4 + 1][c] = v.y;
        ws[q * 4 + 2][c] = v.z; ws[q * 4 + 3][c] = v.w;
    }
    __syncthreads();

    float acc[8][4];
#pragma unroll
    for (int i = 0; i < 8; i++)
#pragma unroll
        for (int j = 0; j < 4; j++) acc[i][j] = 0.0f;

#pragma unroll
    for (int kk = 0; kk < 64; kk++) {
        float4 a0 = *reinterpret_cast<const float4*>(&as[kk][ty * 8]);
        float4 a1 = *reinterpret_cast<const float4*>(&as[kk][ty * 8 + 4]);
        float4 w = *reinterpret_cast<const float4*>(&ws[kk][tx * 4]);
        float av[8] = {a0.x, a0.y, a0.z, a0.w, a1.x, a1.y, a1.z, a1.w};
        float wv[4] = {w.x, w.y, w.z, w.w};
#pragma unroll
        for (int i = 0; i < 8; i++)
#pragma unroll
            for (int j = 0; j < 4; j++) acc[i][j] = fmaf(av[i], wv[j], acc[i][j]);
    }

    float bias[4];
#pragma unroll
    for (int j = 0; j < 4; j++) bias[j] = bdt[col0 + tx * 4 + j];
#pragma unroll
    for (int i = 0; i < 8; i++) {
        float4 r;
        float* rp = &r.x;
#pragma unroll
        for (int j = 0; j < 4; j++) {
            float v = acc[i][j] + bias[j];
            rp[j] = (v > 20.0f) ? v : log1pf(__expf(v));
        }
        *reinterpret_cast<float4*>(
            g_dt + (size_t)(row0 + ty * 8 + i) * DD + col0 + tx * 4) = r;
    }
}

// ---------------- kernel 3: pass 1 — per-chunk local scan ------------------
__global__ __launch_bounds__(256, 6) void scan_pass1(const float* __restrict__ x,
                                                     const float* __restrict__ logA) {
    __shared__ float sdt[CH][128];
    __shared__ float sx[CH][128];
    __shared__ float Bv[CH * NST];
    const int tid = threadIdx.x;
    const int dloc = tid >> 1;
    const int d0 = blockIdx.x * 128;
    const int nb = (tid & 1) * 8;
    const int c = blockIdx.y;
    const int b = blockIdx.z;

    const size_t rowbase = (size_t)(b * TT + c * CH) * DD + d0;
#pragma unroll
    for (int i = 0; i < 2; i++) {
        int lin = tid + i * 256;
        int t = lin >> 5, q = lin & 31;
        *reinterpret_cast<float4*>(&sdt[t][q * 4]) =
            *reinterpret_cast<const float4*>(g_dt + rowbase + (size_t)t * DD + q * 4);
        *reinterpret_cast<float4*>(&sx[t][q * 4]) =
            *reinterpret_cast<const float4*>(x + rowbase + (size_t)t * DD + q * 4);
    }
    {
        int t = tid >> 4, n = tid & 15;
        float A = -__expf(logA[n]);
        Bv[tid] = g_proj[(size_t)(b * TT + c * CH + t) * PCOLS + n] / (A + 1e-8f);
    }

    float An2[8], h[8];
#pragma unroll
    for (int j = 0; j < 8; j++) {
        An2[j] = -__expf(logA[nb + j]) * LOG2E;
        h[j] = 0.0f;
    }
    __syncthreads();

    float sumdt = 0.0f;
#pragma unroll
    for (int t = 0; t < CH; t++) {
        float dtv = sdt[t][dloc];
        float xv = sx[t][dloc];
        sumdt += dtv;
        float4 b0 = *reinterpret_cast<const float4*>(&Bv[t * NST + nb]);
        float4 b1 = *reinterpret_cast<const float4*>(&Bv[t * NST + nb + 4]);
        float bv[8] = {b0.x, b0.y, b0.z, b0.w, b1.x, b1.y, b1.z, b1.w};
#pragma unroll
        for (int j = 0; j < 8; j++) {
            float a = ex2(dtv * An2[j]);
            float g = xv * bv[j];
            h[j] = fmaf(a, h[j] + g, -g);
        }
    }

    const int d = d0 + dloc;
    size_t base = (((size_t)b * NC + c) * DD + d) * NST + nb;
    float4 P0 = {ex2(An2[0] * sumdt), ex2(An2[1] * sumdt),
                 ex2(An2[2] * sumdt), ex2(An2[3] * sumdt)};
    float4 P1 = {ex2(An2[4] * sumdt), ex2(An2[5] * sumdt),
                 ex2(An2[6] * sumdt), ex2(An2[7] * sumdt)};
    *reinterpret_cast<float4*>(g_P + base)     = P0;
    *reinterpret_cast<float4*>(g_P + base + 4) = P1;
    float4 H0 = {h[0], h[1], h[2], h[3]};
    float4 H1 = {h[4], h[5], h[6], h[7]};
    *reinterpret_cast<float4*>(g_H + base)     = H0;
    *reinterpret_cast<float4*>(g_H + base + 4) = H1;
}

// ---------------- kernel 4: combine chunks ---------------------------------
__global__ __launch_bounds__(256) void combine() {
    int idx = blockIdx.x * 256 + threadIdx.x;
    int b = idx / (DD * NST);
    int rem = idx - b * (DD * NST);
    float run = 0.0f;
#pragma unroll 16
    for (int c = 0; c < NC; c++) {
        size_t off = ((size_t)b * NC + c) * (DD * NST) + rem;
        float P = g_P[off];
        float H = g_H[off];
        float nw = fmaf(P, run, H);
        g_H[off] = run;
        run = nw;
    }
}

// ---------------- kernel 5: pass 2 — re-scan with correct init, emit y -----
__global__ __launch_bounds__(256, 6) void scan_pass2(const float* __restrict__ x,
                                                     const float* __restrict__ logA,
                                                     const float* __restrict__ Dskip,
                                                     float* __restrict__ out) {
    __shared__ float sdt[CH][128];
    __shared__ float sx[CH][128];
    __shared__ float sy[CH][128];
    __shared__ float Bv[CH * NST];
    __shared__ float Cs[CH * NST];
    const int tid = threadIdx.x;
    const int dloc = tid >> 1;
    const int d0 = blockIdx.x * 128;
    const int nh = tid & 1;
    const int nb = nh * 8;
    const int c = blockIdx.y;
    const int b = blockIdx.z;

    const size_t rowbase = (size_t)(b * TT + c * CH) * DD + d0;
#pragma unroll
    for (int i = 0; i < 2; i++) {
        int lin = tid + i * 256;
        int t = lin >> 5, q = lin & 31;
        *reinterpret_cast<float4*>(&sdt[t][q * 4]) =
            *reinterpret_cast<const float4*>(g_dt + rowbase + (size_t)t * DD + q * 4);
        *reinterpret_cast<float4*>(&sx[t][q * 4]) =
            *reinterpret_cast<const float4*>(x + rowbase + (size_t)t * DD + q * 4);
    }
    {
        int t = tid >> 4, n = tid & 15;
        float A = -__expf(logA[n]);
        size_t prow = (size_t)(b * TT + c * CH + t) * PCOLS;
        Bv[tid] = g_proj[prow + n] / (A + 1e-8f);
        Cs[tid] = g_proj[prow + 16 + n];
    }

    const int d = d0 + dloc;
    float An2[8], h[8];
    size_t base = (((size_t)b * NC + c) * DD + d) * NST + nb;
    float4 H0 = *reinterpret_cast<const float4*>(g_H + base);
    float4 H1 = *reinterpret_cast<const float4*>(g_H + base + 4);
    h[0] = H0.x; h[1] = H0.y; h[2] = H0.z; h[3] = H0.w;
    h[4] = H1.x; h[5] = H1.y; h[6] = H1.z; h[7] = H1.w;
#pragma unroll
    for (int j = 0; j < 8; j++)
        An2[j] = -__expf(logA[nb + j]) * LOG2E;
    const float dsk = Dskip[d];
    __syncthreads();

#pragma unroll
    for (int t = 0; t < CH; t++) {
        float dtv = sdt[t][dloc];
        float xv = sx[t][dloc];
        float4 b0 = *reinterpret_cast<const float4*>(&Bv[t * NST + nb]);
        float4 b1 = *reinterpret_cast<const float4*>(&Bv[t * NST + nb + 4]);
        float bv[8] = {b0.x, b0.y, b0.z, b0.w, b1.x, b1.y, b1.z, b1.w};
        float4 c0 = *reinterpret_cast<const float4*>(&Cs[t * NST + nb]);
        float4 c1 = *reinterpret_cast<const float4*>(&Cs[t * NST + nb + 4]);
        float cv[8] = {c0.x, c0.y, c0.z, c0.w, c1.x, c1.y, c1.z, c1.w};
        float y = 0.0f;
#pragma unroll
        for (int j = 0; j < 8; j++) {
            float a = ex2(dtv * An2[j]);
            float g = xv * bv[j];
            h[j] = fmaf(a, h[j] + g, -g);
            y = fmaf(h[j], cv[j], y);
        }
        y += __shfl_xor_sync(0xffffffffu, y, 1);
        if (nh == 0) sy[t][dloc] = fmaf(dsk, xv, y);
    }
    __syncthreads();

#pragma unroll
    for (int i = 0; i < 2; i++) {
        int lin = tid + i * 256;
        int t = lin >> 5, q = lin & 31;
        *reinterpret_cast<float4*>(out + rowbase + (size_t)t * DD + q * 4) =
            *reinterpret_cast<const float4*>(&sy[t][q * 4]);
    }
}

// ---------------- launcher -------------------------------------------------
extern "C" void kernel_launch(void* const* d_in, const int* in_sizes, int n_in,
                              void* d_out, int out_size) {
    const float* x    = (const float*)d_in[0];
    const float* WB   = (const float*)d_in[1];
    const float* WC   = (const float*)d_in[2];
    const float* Wdt1 = (const float*)d_in[3];
    const float* Wdt2 = (const float*)d_in[4];
    const float* bdt2 = (const float*)d_in[5];
    const float* logA = (const float*)d_in[6];
    const float* Dsk  = (const float*)d_in[7];
    float* out = (float*)d_out;

    proj_mma<<<dim3(BT / 128, KSPLIT), 256>>>(x, WB, WC, Wdt1);
    reduce_proj<<<(BT * PCOLS / 4 + 255) / 256, 256>>>();
    dt_gemm<<<dim3(BT / 128, DD / 64), 256>>>(Wdt2, bdt2);
    scan_pass1<<<dim3(DD / 128, NC, BSZ), 256>>>(x, logA);
    combine<<<(BSZ * DD * NST) / 256, 256>>>();
    scan_pass2<<<dim3(DD / 128, NC, BSZ), 256>>>(x, logA, Dsk, out);
}

// round 11
// speedup vs baseline: 1.4669x; 1.0273x over previous
#include <cuda_runtime.h>
#include <cuda_bf16.h>
#include <math.h>

#define BSZ 2
#define TT 2048
#define DD 1024
#define NST 16
#define RK 64
#define BT (BSZ*TT)          // 4096
#define NC 128               // chunks
#define CH (TT/NC)           // 16 steps per chunk
#define PCOLS 96             // 16 B + 16 C + 64 R
#define KSPLIT 8
#define LOG2E 1.44269504f

__device__ __forceinline__ float ex2(float v) {
    float r; asm("ex2.approx.f32 %0, %1;" : "=f"(r) : "f"(v)); return r;
}
__device__ __forceinline__ float rcpa(float v) {
    float r; asm("rcp.approx.f32 %0, %1;" : "=f"(r) : "f"(v)); return r;
}

// ---------------- scratch (static device memory; no allocs allowed) --------
__device__ float g_part[KSPLIT * BT * PCOLS]; // split-K partials
__device__ float g_proj[BT * PCOLS];          // col 0-15 = B_t, 16-31 = C_t, 32-95 = R
__device__ float g_dt[BT * DD];               // softplus(dt_raw)
__device__ float g_P[BSZ * NC * DD * NST];    // per-chunk product of a_t
__device__ float g_H[BSZ * NC * DD * NST];    // chunk-local final h -> becomes init h

// split one float4 into two packed bf16x4 (hi, lo)
__device__ __forceinline__ void split4(float4 v, uint2& hw, uint2& lw) {
    float f[4] = {v.x, v.y, v.z, v.w};
    unsigned h[2], l[2];
#pragma unroll
    for (int k = 0; k < 2; k++) {
        __nv_bfloat16 h0 = __float2bfloat16(f[2 * k]);
        __nv_bfloat16 h1 = __float2bfloat16(f[2 * k + 1]);
        __nv_bfloat16 l0 = __float2bfloat16(f[2 * k] - __bfloat162float(h0));
        __nv_bfloat16 l1 = __float2bfloat16(f[2 * k + 1] - __bfloat162float(h1));
        h[k] = (unsigned)__bfloat16_as_ushort(h0) | ((unsigned)__bfloat16_as_ushort(h1) << 16);
        l[k] = (unsigned)__bfloat16_as_ushort(l0) | ((unsigned)__bfloat16_as_ushort(l1) << 16);
    }
    hw = make_uint2(h[0], h[1]);
    lw = make_uint2(l[0], l[1]);
}

__device__ __forceinline__ void mma_bf16(float* d, const unsigned* a,
                                         unsigned b0, unsigned b1) {
    asm("mma.sync.aligned.m16n8k16.row.col.f32.bf16.bf16.f32 "
        "{%0,%1,%2,%3}, {%4,%5,%6,%7}, {%8,%9}, {%0,%1,%2,%3};"
        : "+f"(d[0]), "+f"(d[1]), "+f"(d[2]), "+f"(d[3])
        : "r"(a[0]), "r"(a[1]), "r"(a[2]), "r"(a[3]), "r"(b0), "r"(b1));
}

// ---------------- kernel 1: proj GEMM via tensor cores ---------------------
// grid (BT/128, KSPLIT=8), block 256. 128 K per block (4 k-tiles of 32).
__global__ __launch_bounds__(256) void proj_mma(const float* __restrict__ x,
                                                const float* __restrict__ WB,
                                                const float* __restrict__ WC,
                                                const float* __restrict__ Wdt1) {
    __shared__ __nv_bfloat16 Ahi[128][40];
    __shared__ __nv_bfloat16 Alo[128][40];
    __shared__ __nv_bfloat16 Bhi[96][40];
    __shared__ __nv_bfloat16 Blo[96][40];
    const int tid = threadIdx.x;
    const int lane = tid & 31, wid = tid >> 5;
    const int warpM = wid & 3;              // 4 x 32 rows
    const int warpN = wid >> 2;             // 2 x 48 cols
    const int row0 = blockIdx.x * 128;
    const int kb = blockIdx.y * (DD / KSPLIT);   // 128 K columns per block

    float acc[2][6][4];
#pragma unroll
    for (int mt = 0; mt < 2; mt++)
#pragma unroll
        for (int nt = 0; nt < 6; nt++)
#pragma unroll
            for (int q = 0; q < 4; q++) acc[mt][nt][q] = 0.0f;

#pragma unroll 1
    for (int kt = 0; kt < 4; kt++) {
        const int kcur = kb + kt * 32;
#pragma unroll
        for (int i = 0; i < 4; i++) {
            int lin = tid + i * 256;            // 1024 float4
            int r = lin >> 3, q = lin & 7;
            float4 v = *reinterpret_cast<const float4*>(
                x + (size_t)(row0 + r) * DD + kcur + q * 4);
            uint2 hw, lw;
            split4(v, hw, lw);
            *reinterpret_cast<uint2*>(&Ahi[r][q * 4]) = hw;
            *reinterpret_cast<uint2*>(&Alo[r][q * 4]) = lw;
        }
#pragma unroll
        for (int i = 0; i < 3; i++) {
            int lin = tid + i * 256;
            if (lin < 768) {
                int n = lin >> 3, q = lin & 7;
                const float* src = (n < 16) ? (WB + (size_t)n * DD)
                                  : (n < 32) ? (WC + (size_t)(n - 16) * DD)
                                             : (Wdt1 + (size_t)(n - 32) * DD);
                float4 v = *reinterpret_cast<const float4*>(src + kcur + q * 4);
                uint2 hw, lw;
                split4(v, hw, lw);
                *reinterpret_cast<uint2*>(&Bhi[n][q * 4]) = hw;
                *reinterpret_cast<uint2*>(&Blo[n][q * 4]) = lw;
            }
        }
        __syncthreads();

#pragma unroll
        for (int seg = 0; seg < 3; seg++) {
            const __nv_bfloat16 (*Asp)[40] = (seg < 2) ? Ahi : Alo;
            const __nv_bfloat16 (*Bsp)[40] = (seg == 1) ? Blo : Bhi;
#pragma unroll
            for (int k16 = 0; k16 < 32; k16 += 16) {
                const int ccol = k16 + (lane & 3) * 2;
                unsigned a[2][4];
#pragma unroll
                for (int mt = 0; mt < 2; mt++) {
                    int r = warpM * 32 + mt * 16 + (lane >> 2);
                    a[mt][0] = *reinterpret_cast<const unsigned*>(&Asp[r][ccol]);
                    a[mt][1] = *reinterpret_cast<const unsigned*>(&Asp[r + 8][ccol]);
                    a[mt][2] = *reinterpret_cast<const unsigned*>(&Asp[r][ccol + 8]);
                    a[mt][3] = *reinterpret_cast<const unsigned*>(&Asp[r + 8][ccol + 8]);
                }
#pragma unroll
                for (int nt = 0; nt < 6; nt++) {
                    int n = warpN * 48 + nt * 8 + (lane >> 2);
                    unsigned b0 = *reinterpret_cast<const unsigned*>(&Bsp[n][ccol]);
                    unsigned b1 = *reinterpret_cast<const unsigned*>(&Bsp[n][ccol + 8]);
                    mma_bf16(acc[0][nt], a[0], b0, b1);
                    mma_bf16(acc[1][nt], a[1], b0, b1);
                }
            }
        }
        __syncthreads();
    }

    float* outp = g_part + (size_t)blockIdx.y * BT * PCOLS;
#pragma unroll
    for (int mt = 0; mt < 2; mt++)
#pragma unroll
        for (int nt = 0; nt < 6; nt++) {
            int r = row0 + warpM * 32 + mt * 16 + (lane >> 2);
            int c = warpN * 48 + nt * 8 + (lane & 3) * 2;
            float2 v0 = {acc[mt][nt][0], acc[mt][nt][1]};
            float2 v1 = {acc[mt][nt][2], acc[mt][nt][3]};
            *reinterpret_cast<float2*>(&outp[(size_t)r * PCOLS + c]) = v0;
            *reinterpret_cast<float2*>(&outp[(size_t)(r + 8) * PCOLS + c]) = v1;
        }
}

// ---------------- kernel 1b: reduce split-K partials (float4) --------------
__global__ __launch_bounds__(256) void reduce_proj() {
    int i = blockIdx.x * 256 + threadIdx.x;     // float4 index
    if (i < BT * PCOLS / 4) {
        float4 s = {0.f, 0.f, 0.f, 0.f};
#pragma unroll
        for (int k = 0; k < KSPLIT; k++) {
            float4 v = reinterpret_cast<const float4*>(g_part)[(size_t)k * (BT * PCOLS / 4) + i];
            s.x += v.x; s.y += v.y; s.z += v.z; s.w += v.w;
        }
        reinterpret_cast<float4*>(g_proj)[i] = s;
    }
}

// ---------------- kernel 2: dt GEMM via tensor cores (resident smem) -------
// C[4096x1024] = R[4096x64] @ W2^T, bf16 2-term split, 3 segments from
// RESIDENT smem (single global load). grid (BT/128, DD/128), block 256.
__global__ __launch_bounds__(256) void dt_mma(const float* __restrict__ W2,
                                              const float* __restrict__ bdt) {
    __shared__ __nv_bfloat16 Ahi[128][72];
    __shared__ __nv_bfloat16 Alo[128][72];
    __shared__ __nv_bfloat16 Bhi[128][72];
    __shared__ __nv_bfloat16 Blo[128][72];
    const int tid = threadIdx.x;
    const int lane = tid & 31, wid = tid >> 5;
    const int warpM = wid & 3;              // 4 x 32 rows
    const int warpN = wid >> 2;             // 2 x 64 cols
    const int row0 = blockIdx.x * 128;
    const int col0 = blockIdx.y * 128;

    // stage A = R (g_proj cols 32..95) 128x64, split hi/lo
#pragma unroll
    for (int i = 0; i < 8; i++) {
        int lin = tid + i * 256;                // 2048 float4
        int r = lin >> 4, q = lin & 15;
        float4 v = *reinterpret_cast<const float4*>(
            g_proj + (size_t)(row0 + r) * PCOLS + 32 + q * 4);
        uint2 hw, lw;
        split4(v, hw, lw);
        *reinterpret_cast<uint2*>(&Ahi[r][q * 4]) = hw;
        *reinterpret_cast<uint2*>(&Alo[r][q * 4]) = lw;
    }
    // stage B = W2 rows col0..col0+127, 128x64, split hi/lo
#pragma unroll
    for (int i = 0; i < 8; i++) {
        int lin = tid + i * 256;
        int n = lin >> 4, q = lin & 15;
        float4 v = *reinterpret_cast<const float4*>(
            W2 + (size_t)(col0 + n) * RK + q * 4);
        uint2 hw, lw;
        split4(v, hw, lw);
        *reinterpret_cast<uint2*>(&Bhi[n][q * 4]) = hw;
        *reinterpret_cast<uint2*>(&Blo[n][q * 4]) = lw;
    }
    __syncthreads();

    float acc[2][8][4];
#pragma unroll
    for (int mt = 0; mt < 2; mt++)
#pragma unroll
        for (int nt = 0; nt < 8; nt++)
#pragma unroll
            for (int q = 0; q < 4; q++) acc[mt][nt][q] = 0.0f;

#pragma unroll
    for (int seg = 0; seg < 3; seg++) {
        const __nv_bfloat16 (*Asp)[72] = (seg < 2) ? Ahi : Alo;
        const __nv_bfloat16 (*Bsp)[72] = (seg == 1) ? Blo : Bhi;
#pragma unroll
        for (int k16 = 0; k16 < 64; k16 += 16) {
            const int ccol = k16 + (lane & 3) * 2;
            unsigned a[2][4];
#pragma unroll
            for (int mt = 0; mt < 2; mt++) {
                int r = warpM * 32 + mt * 16 + (lane >> 2);
                a[mt][0] = *reinterpret_cast<const unsigned*>(&Asp[r][ccol]);
                a[mt][1] = *reinterpret_cast<const unsigned*>(&Asp[r + 8][ccol]);
                a[mt][2] = *reinterpret_cast<const unsigned*>(&Asp[r][ccol + 8]);
                a[mt][3] = *reinterpret_cast<const unsigned*>(&Asp[r + 8][ccol + 8]);
            }
#pragma unroll
            for (int nt = 0; nt < 8; nt++) {
                int n = warpN * 64 + nt * 8 + (lane >> 2);
                unsigned b0 = *reinterpret_cast<const unsigned*>(&Bsp[n][ccol]);
                unsigned b1 = *reinterpret_cast<const unsigned*>(&Bsp[n][ccol + 8]);
                mma_bf16(acc[0][nt], a[0], b0, b1);
                mma_bf16(acc[1][nt], a[1], b0, b1);
            }
        }
    }

#pragma unroll
    for (int mt = 0; mt < 2; mt++)
#pragma unroll
        for (int nt = 0; nt < 8; nt++) {
            int r = row0 + warpM * 32 + mt * 16 + (lane >> 2);
            int c = col0 + warpN * 64 + nt * 8 + (lane & 3) * 2;
            float b0 = bdt[c], b1 = bdt[c + 1];
            float v0 = acc[mt][nt][0] + b0;
            float v1 = acc[mt][nt][1] + b1;
            float v2 = acc[mt][nt][2] + b0;
            float v3 = acc[mt][nt][3] + b1;
            float2 r0 = {(v0 > 20.0f) ? v0 : log1pf(__expf(v0)),
                         (v1 > 20.0f) ? v1 : log1pf(__expf(v1))};
            float2 r1 = {(v2 > 20.0f) ? v2 : log1pf(__expf(v2)),
                         (v3 > 20.0f) ? v3 : log1pf(__expf(v3))};
            *reinterpret_cast<float2*>(&g_dt[(size_t)r * DD + c]) = r0;
            *reinterpret_cast<float2*>(&g_dt[(size_t)(r + 8) * DD + c]) = r1;
        }
}

// ---------------- kernel 3: pass 1 — per-chunk local scan ------------------
__global__ __launch_bounds__(256, 6) void scan_pass1(const float* __restrict__ x,
                                                     const float* __restrict__ logA) {
    __shared__ float sdt[CH][128];
    __shared__ float sx[CH][128];
    __shared__ float Bv[CH * NST];
    const int tid = threadIdx.x;
    const int dloc = tid >> 1;
    const int d0 = blockIdx.x * 128;
    const int nb = (tid & 1) * 8;
    const int c = blockIdx.y;
    const int b = blockIdx.z;

    const size_t rowbase = (size_t)(b * TT + c * CH) * DD + d0;
#pragma unroll
    for (int i = 0; i < 2; i++) {
        int lin = tid + i * 256;
        int t = lin >> 5, q = lin & 31;
        *reinterpret_cast<float4*>(&sdt[t][q * 4]) =
            *reinterpret_cast<const float4*>(g_dt + rowbase + (size_t)t * DD + q * 4);
        *reinterpret_cast<float4*>(&sx[t][q * 4]) =
            *reinterpret_cast<const float4*>(x + rowbase + (size_t)t * DD + q * 4);
    }
    {
        int t = tid >> 4, n = tid & 15;
        float A = -ex2(logA[n] * LOG2E);
        Bv[tid] = g_proj[(size_t)(b * TT + c * CH + t) * PCOLS + n] * rcpa(A + 1e-8f);
    }

    float An2[8], h[8];
#pragma unroll
    for (int j = 0; j < 8; j++) {
        An2[j] = -ex2(logA[nb + j] * LOG2E) * LOG2E;
        h[j] = 0.0f;
    }
    __syncthreads();

    float sumdt = 0.0f;
#pragma unroll
    for (int t = 0; t < CH; t++) {
        float dtv = sdt[t][dloc];
        float xv = sx[t][dloc];
        sumdt += dtv;
        float4 b0 = *reinterpret_cast<const float4*>(&Bv[t * NST + nb]);
        float4 b1 = *reinterpret_cast<const float4*>(&Bv[t * NST + nb + 4]);
        float bv[8] = {b0.x, b0.y, b0.z, b0.w, b1.x, b1.y, b1.z, b1.w};
#pragma unroll
        for (int j = 0; j < 8; j++) {
            float a = ex2(dtv * An2[j]);
            float g = xv * bv[j];
            h[j] = fmaf(a, h[j] + g, -g);
        }
    }

    const int d = d0 + dloc;
    size_t base = (((size_t)b * NC + c) * DD + d) * NST + nb;
    float4 P0 = {ex2(An2[0] * sumdt), ex2(An2[1] * sumdt),
                 ex2(An2[2] * sumdt), ex2(An2[3] * sumdt)};
    float4 P1 = {ex2(An2[4] * sumdt), ex2(An2[5] * sumdt),
                 ex2(An2[6] * sumdt), ex2(An2[7] * sumdt)};
    *reinterpret_cast<float4*>(g_P + base)     = P0;
    *reinterpret_cast<float4*>(g_P + base + 4) = P1;
    float4 H0 = {h[0], h[1], h[2], h[3]};
    float4 H1 = {h[4], h[5], h[6], h[7]};
    *reinterpret_cast<float4*>(g_H + base)     = H0;
    *reinterpret_cast<float4*>(g_H + base + 4) = H1;
}

// ---------------- kernel 4: combine chunks ---------------------------------
__global__ __launch_bounds__(256) void combine() {
    int idx = blockIdx.x * 256 + threadIdx.x;
    int b = idx / (DD * NST);
    int rem = idx - b * (DD * NST);
    float run = 0.0f;
#pragma unroll 16
    for (int c = 0; c < NC; c++) {
        size_t off = ((size_t)b * NC + c) * (DD * NST) + rem;
        float P = g_P[off];
        float H = g_H[off];
        float nw = fmaf(P, run, H);
        g_H[off] = run;
        run = nw;
    }
}

// ---------------- kernel 5: pass 2 — re-scan with correct init, emit y -----
__global__ __launch_bounds__(256, 6) void scan_pass2(const float* __restrict__ x,
                                                     const float* __restrict__ logA,
                                                     const float* __restrict__ Dskip,
                                                     float* __restrict__ out) {
    __shared__ float sdt[CH][128];
    __shared__ float sx[CH][128];
    __shared__ float sy[CH][128];
    __shared__ float Bv[CH * NST];
    __shared__ float Cs[CH * NST];
    const int tid = threadIdx.x;
    const int dloc = tid >> 1;
    const int d0 = blockIdx.x * 128;
    const int nh = tid & 1;
    const int nb = nh * 8;
    const int c = blockIdx.y;
    const int b = blockIdx.z;

    const size_t rowbase = (size_t)(b * TT + c * CH) * DD + d0;
#pragma unroll
    for (int i = 0; i < 2; i++) {
        int lin = tid + i * 256;
        int t = lin >> 5, q = lin & 31;
        *reinterpret_cast<float4*>(&sdt[t][q * 4]) =
            *reinterpret_cast<const float4*>(g_dt + rowbase + (size_t)t * DD + q * 4);
        *reinterpret_cast<float4*>(&sx[t][q * 4]) =
            *reinterpret_cast<const float4*>(x + rowbase + (size_t)t * DD + q * 4);
    }
    {
        int t = tid >> 4, n = tid & 15;
        float A = -ex2(logA[n] * LOG2E);
        size_t prow = (size_t)(b * TT + c * CH + t) * PCOLS;
        Bv[tid] = g_proj[prow + n] * rcpa(A + 1e-8f);
        Cs[tid] = g_proj[prow + 16 + n];
    }

    const int d = d0 + dloc;
    float An2[8], h[8];
    size_t base = (((size_t)b * NC + c) * DD + d) * NST + nb;
    float4 H0 = *reinterpret_cast<const float4*>(g_H + base);
    float4 H1 = *reinterpret_cast<const float4*>(g_H + base + 4);
    h[0] = H0.x; h[1] = H0.y; h[2] = H0.z; h[3] = H0.w;
    h[4] = H1.x; h[5] = H1.y; h[6] = H1.z; h[7] = H1.w;
#pragma unroll
    for (int j = 0; j < 8; j++)
        An2[j] = -ex2(logA[nb + j] * LOG2E) * LOG2E;
    const float dsk = Dskip[d];
    __syncthreads();

#pragma unroll
    for (int t = 0; t < CH; t++) {
        float dtv = sdt[t][dloc];
        float xv = sx[t][dloc];
        float4 b0 = *reinterpret_cast<const float4*>(&Bv[t * NST + nb]);
        float4 b1 = *reinterpret_cast<const float4*>(&Bv[t * NST + nb + 4]);
        float bv[8] = {b0.x, b0.y, b0.z, b0.w, b1.x, b1.y, b1.z, b1.w};
        float4 c0 = *reinterpret_cast<const float4*>(&Cs[t * NST + nb]);
        float4 c1 = *reinterpret_cast<const float4*>(&Cs[t * NST + nb + 4]);
        float cv[8] = {c0.x, c0.y, c0.z, c0.w, c1.x, c1.y, c1.z, c1.w};
        float y = 0.0f;
#pragma unroll
        for (int j = 0; j < 8; j++) {
            float a = ex2(dtv * An2[j]);
            float g = xv * bv[j];
            h[j] = fmaf(a, h[j] + g, -g);
            y = fmaf(h[j], cv[j], y);
        }
        y += __shfl_xor_sync(0xffffffffu, y, 1);
        if (nh == 0) sy[t][dloc] = fmaf(dsk, xv, y);
    }
    __syncthreads();

#pragma unroll
    for (int i = 0; i < 2; i++) {
        int lin = tid + i * 256;
        int t = lin >> 5, q = lin & 31;
        *reinterpret_cast<float4*>(out + rowbase + (size_t)t * DD + q * 4) =
            *reinterpret_cast<const float4*>(&sy[t][q * 4]);
    }
}

// ---------------- launcher -------------------------------------------------
extern "C" void kernel_launch(void* const* d_in, const int* in_sizes, int n_in,
                              void* d_out, int out_size) {
    const float* x    = (const float*)d_in[0];
    const float* WB   = (const float*)d_in[1];
    const float* WC   = (const float*)d_in[2];
    const float* Wdt1 = (const float*)d_in[3];
    const float* Wdt2 = (const float*)d_in[4];
    const float* bdt2 = (const float*)d_in[5];
    const float* logA = (const float*)d_in[6];
    const float* Dsk  = (const float*)d_in[7];
    float* out = (float*)d_out;

    proj_mma<<<dim3(BT / 128, KSPLIT), 256>>>(x, WB, WC, Wdt1);
    reduce_proj<<<(BT * PCOLS / 4 + 255) / 256, 256>>>();
    dt_mma<<<dim3(BT / 128, DD / 128), 256>>>(Wdt2, bdt2);
    scan_pass1<<<dim3(DD / 128, NC, BSZ), 256>>>(x, logA);
    combine<<<(BSZ * DD * NST) / 256, 256>>>();
    scan_pass2<<<dim3(DD / 128, NC, BSZ), 256>>>(x, logA, Dsk, out);
}

// round 12
// speedup vs baseline: 1.7140x; 1.1684x over previous
#include <cuda_runtime.h>
#include <cuda_bf16.h>
#include <math.h>

#define BSZ 2
#define TT 2048
#define DD 1024
#define NST 16
#define RK 64
#define BT (BSZ*TT)          // 4096
#define NC 64                // chunks
#define CH (TT/NC)           // 32 steps per chunk
#define PCOLS 96             // 16 B + 16 C + 64 R
#define KSPLIT 8
#define LOG2E 1.44269504f

__device__ __forceinline__ float ex2(float v) {
    float r; asm("ex2.approx.f32 %0, %1;" : "=f"(r) : "f"(v)); return r;
}
__device__ __forceinline__ float rcpa(float v) {
    float r; asm("rcp.approx.f32 %0, %1;" : "=f"(r) : "f"(v)); return r;
}

// ---------------- scratch (static device memory; no allocs allowed) --------
__device__ float g_part[KSPLIT * BT * PCOLS]; // split-K partials
__device__ float g_proj[BT * PCOLS];          // col 0-15 = B_t, 16-31 = C_t, 32-95 = R
__device__ float g_dt[BT * DD];               // softplus(dt_raw)
__device__ float g_P[BSZ * NC * DD * NST];    // per-chunk product of a_t
__device__ float g_H[BSZ * NC * DD * NST];    // chunk-local final h -> becomes init h

// split one float4 into two packed bf16x4 (hi, lo)
__device__ __forceinline__ void split4(float4 v, uint2& hw, uint2& lw) {
    float f[4] = {v.x, v.y, v.z, v.w};
    unsigned h[2], l[2];
#pragma unroll
    for (int k = 0; k < 2; k++) {
        __nv_bfloat16 h0 = __float2bfloat16(f[2 * k]);
        __nv_bfloat16 h1 = __float2bfloat16(f[2 * k + 1]);
        __nv_bfloat16 l0 = __float2bfloat16(f[2 * k] - __bfloat162float(h0));
        __nv_bfloat16 l1 = __float2bfloat16(f[2 * k + 1] - __bfloat162float(h1));
        h[k] = (unsigned)__bfloat16_as_ushort(h0) | ((unsigned)__bfloat16_as_ushort(h1) << 16);
        l[k] = (unsigned)__bfloat16_as_ushort(l0) | ((unsigned)__bfloat16_as_ushort(l1) << 16);
    }
    hw = make_uint2(h[0], h[1]);
    lw = make_uint2(l[0], l[1]);
}

__device__ __forceinline__ void mma_bf16(float* d, const unsigned* a,
                                         unsigned b0, unsigned b1) {
    asm("mma.sync.aligned.m16n8k16.row.col.f32.bf16.bf16.f32 "
        "{%0,%1,%2,%3}, {%4,%5,%6,%7}, {%8,%9}, {%0,%1,%2,%3};"
        : "+f"(d[0]), "+f"(d[1]), "+f"(d[2]), "+f"(d[3])
        : "r"(a[0]), "r"(a[1]), "r"(a[2]), "r"(a[3]), "r"(b0), "r"(b1));
}

// ---------------- kernel 1: proj GEMM via tensor cores ---------------------
// grid (BT/128, KSPLIT=8), block 256. 128 K per block (4 k-tiles of 32).
__global__ __launch_bounds__(256) void proj_mma(const float* __restrict__ x,
                                                const float* __restrict__ WB,
                                                const float* __restrict__ WC,
                                                const float* __restrict__ Wdt1) {
    __shared__ __nv_bfloat16 Ahi[128][40];
    __shared__ __nv_bfloat16 Alo[128][40];
    __shared__ __nv_bfloat16 Bhi[96][40];
    __shared__ __nv_bfloat16 Blo[96][40];
    const int tid = threadIdx.x;
    const int lane = tid & 31, wid = tid >> 5;
    const int warpM = wid & 3;              // 4 x 32 rows
    const int warpN = wid >> 2;             // 2 x 48 cols
    const int row0 = blockIdx.x * 128;
    const int kb = blockIdx.y * (DD / KSPLIT);   // 128 K columns per block

    float acc[2][6][4];
#pragma unroll
    for (int mt = 0; mt < 2; mt++)
#pragma unroll
        for (int nt = 0; nt < 6; nt++)
#pragma unroll
            for (int q = 0; q < 4; q++) acc[mt][nt][q] = 0.0f;

#pragma unroll 1
    for (int kt = 0; kt < 4; kt++) {
        const int kcur = kb + kt * 32;
#pragma unroll
        for (int i = 0; i < 4; i++) {
            int lin = tid + i * 256;            // 1024 float4
            int r = lin >> 3, q = lin & 7;
            float4 v = *reinterpret_cast<const float4*>(
                x + (size_t)(row0 + r) * DD + kcur + q * 4);
            uint2 hw, lw;
            split4(v, hw, lw);
            *reinterpret_cast<uint2*>(&Ahi[r][q * 4]) = hw;
            *reinterpret_cast<uint2*>(&Alo[r][q * 4]) = lw;
        }
#pragma unroll
        for (int i = 0; i < 3; i++) {
            int lin = tid + i * 256;
            if (lin < 768) {
                int n = lin >> 3, q = lin & 7;
                const float* src = (n < 16) ? (WB + (size_t)n * DD)
                                  : (n < 32) ? (WC + (size_t)(n - 16) * DD)
                                             : (Wdt1 + (size_t)(n - 32) * DD);
                float4 v = *reinterpret_cast<const float4*>(src + kcur + q * 4);
                uint2 hw, lw;
                split4(v, hw, lw);
                *reinterpret_cast<uint2*>(&Bhi[n][q * 4]) = hw;
                *reinterpret_cast<uint2*>(&Blo[n][q * 4]) = lw;
            }
        }
        __syncthreads();

#pragma unroll
        for (int seg = 0; seg < 3; seg++) {
            const __nv_bfloat16 (*Asp)[40] = (seg < 2) ? Ahi : Alo;
            const __nv_bfloat16 (*Bsp)[40] = (seg == 1) ? Blo : Bhi;
#pragma unroll
            for (int k16 = 0; k16 < 32; k16 += 16) {
                const int ccol = k16 + (lane & 3) * 2;
                unsigned a[2][4];
#pragma unroll
                for (int mt = 0; mt < 2; mt++) {
                    int r = warpM * 32 + mt * 16 + (lane >> 2);
                    a[mt][0] = *reinterpret_cast<const unsigned*>(&Asp[r][ccol]);
                    a[mt][1] = *reinterpret_cast<const unsigned*>(&Asp[r + 8][ccol]);
                    a[mt][2] = *reinterpret_cast<const unsigned*>(&Asp[r][ccol + 8]);
                    a[mt][3] = *reinterpret_cast<const unsigned*>(&Asp[r + 8][ccol + 8]);
                }
#pragma unroll
                for (int nt = 0; nt < 6; nt++) {
                    int n = warpN * 48 + nt * 8 + (lane >> 2);
                    unsigned b0 = *reinterpret_cast<const unsigned*>(&Bsp[n][ccol]);
                    unsigned b1 = *reinterpret_cast<const unsigned*>(&Bsp[n][ccol + 8]);
                    mma_bf16(acc[0][nt], a[0], b0, b1);
                    mma_bf16(acc[1][nt], a[1], b0, b1);
                }
            }
        }
        __syncthreads();
    }

    float* outp = g_part + (size_t)blockIdx.y * BT * PCOLS;
#pragma unroll
    for (int mt = 0; mt < 2; mt++)
#pragma unroll
        for (int nt = 0; nt < 6; nt++) {
            int r = row0 + warpM * 32 + mt * 16 + (lane >> 2);
            int c = warpN * 48 + nt * 8 + (lane & 3) * 2;
            float2 v0 = {acc[mt][nt][0], acc[mt][nt][1]};
            float2 v1 = {acc[mt][nt][2], acc[mt][nt][3]};
            *reinterpret_cast<float2*>(&outp[(size_t)r * PCOLS + c]) = v0;
            *reinterpret_cast<float2*>(&outp[(size_t)(r + 8) * PCOLS + c]) = v1;
        }
}

// ---------------- kernel 1b: reduce split-K partials (float4) --------------
__global__ __launch_bounds__(256) void reduce_proj() {
    int i = blockIdx.x * 256 + threadIdx.x;     // float4 index
    if (i < BT * PCOLS / 4) {
        float4 s = {0.f, 0.f, 0.f, 0.f};
#pragma unroll
        for (int k = 0; k < KSPLIT; k++) {
            float4 v = reinterpret_cast<const float4*>(g_part)[(size_t)k * (BT * PCOLS / 4) + i];
            s.x += v.x; s.y += v.y; s.z += v.z; s.w += v.w;
        }
        reinterpret_cast<float4*>(g_proj)[i] = s;
    }
}

// ---------------- kernel 2: dt GEMM via tensor cores (resident smem) -------
__global__ __launch_bounds__(256) void dt_mma(const float* __restrict__ W2,
                                              const float* __restrict__ bdt) {
    __shared__ __nv_bfloat16 Ahi[128][72];
    __shared__ __nv_bfloat16 Alo[128][72];
    __shared__ __nv_bfloat16 Bhi[128][72];
    __shared__ __nv_bfloat16 Blo[128][72];
    const int tid = threadIdx.x;
    const int lane = tid & 31, wid = tid >> 5;
    const int warpM = wid & 3;              // 4 x 32 rows
    const int warpN = wid >> 2;             // 2 x 64 cols
    const int row0 = blockIdx.x * 128;
    const int col0 = blockIdx.y * 128;

#pragma unroll
    for (int i = 0; i < 8; i++) {
        int lin = tid + i * 256;                // 2048 float4
        int r = lin >> 4, q = lin & 15;
        float4 v = *reinterpret_cast<const float4*>(
            g_proj + (size_t)(row0 + r) * PCOLS + 32 + q * 4);
        uint2 hw, lw;
        split4(v, hw, lw);
        *reinterpret_cast<uint2*>(&Ahi[r][q * 4]) = hw;
        *reinterpret_cast<uint2*>(&Alo[r][q * 4]) = lw;
    }
#pragma unroll
    for (int i = 0; i < 8; i++) {
        int lin = tid + i * 256;
        int n = lin >> 4, q = lin & 15;
        float4 v = *reinterpret_cast<const float4*>(
            W2 + (size_t)(col0 + n) * RK + q * 4);
        uint2 hw, lw;
        split4(v, hw, lw);
        *reinterpret_cast<uint2*>(&Bhi[n][q * 4]) = hw;
        *reinterpret_cast<uint2*>(&Blo[n][q * 4]) = lw;
    }
    __syncthreads();

    float acc[2][8][4];
#pragma unroll
    for (int mt = 0; mt < 2; mt++)
#pragma unroll
        for (int nt = 0; nt < 8; nt++)
#pragma unroll
            for (int q = 0; q < 4; q++) acc[mt][nt][q] = 0.0f;

#pragma unroll
    for (int seg = 0; seg < 3; seg++) {
        const __nv_bfloat16 (*Asp)[72] = (seg < 2) ? Ahi : Alo;
        const __nv_bfloat16 (*Bsp)[72] = (seg == 1) ? Blo : Bhi;
#pragma unroll
        for (int k16 = 0; k16 < 64; k16 += 16) {
            const int ccol = k16 + (lane & 3) * 2;
            unsigned a[2][4];
#pragma unroll
            for (int mt = 0; mt < 2; mt++) {
                int r = warpM * 32 + mt * 16 + (lane >> 2);
                a[mt][0] = *reinterpret_cast<const unsigned*>(&Asp[r][ccol]);
                a[mt][1] = *reinterpret_cast<const unsigned*>(&Asp[r + 8][ccol]);
                a[mt][2] = *reinterpret_cast<const unsigned*>(&Asp[r][ccol + 8]);
                a[mt][3] = *reinterpret_cast<const unsigned*>(&Asp[r + 8][ccol + 8]);
            }
#pragma unroll
            for (int nt = 0; nt < 8; nt++) {
                int n = warpN * 64 + nt * 8 + (lane >> 2);
                unsigned b0 = *reinterpret_cast<const unsigned*>(&Bsp[n][ccol]);
                unsigned b1 = *reinterpret_cast<const unsigned*>(&Bsp[n][ccol + 8]);
                mma_bf16(acc[0][nt], a[0], b0, b1);
                mma_bf16(acc[1][nt], a[1], b0, b1);
            }
        }
    }

#pragma unroll
    for (int mt = 0; mt < 2; mt++)
#pragma unroll
        for (int nt = 0; nt < 8; nt++) {
            int r = row0 + warpM * 32 + mt * 16 + (lane >> 2);
            int c = col0 + warpN * 64 + nt * 8 + (lane & 3) * 2;
            float b0 = bdt[c], b1 = bdt[c + 1];
            float v0 = acc[mt][nt][0] + b0;
            float v1 = acc[mt][nt][1] + b1;
            float v2 = acc[mt][nt][2] + b0;
            float v3 = acc[mt][nt][3] + b1;
            float2 r0 = {(v0 > 20.0f) ? v0 : log1pf(__expf(v0)),
                         (v1 > 20.0f) ? v1 : log1pf(__expf(v1))};
            float2 r1 = {(v2 > 20.0f) ? v2 : log1pf(__expf(v2)),
                         (v3 > 20.0f) ? v3 : log1pf(__expf(v3))};
            *reinterpret_cast<float2*>(&g_dt[(size_t)r * DD + c]) = r0;
            *reinterpret_cast<float2*>(&g_dt[(size_t)(r + 8) * DD + c]) = r1;
        }
}

// ---------------- kernel 3: pass 1 — per-chunk local scan (CH=32) ----------
__global__ __launch_bounds__(256, 6) void scan_pass1(const float* __restrict__ x,
                                                     const float* __restrict__ logA) {
    __shared__ float sdt[CH][128];
    __shared__ float sx[CH][128];
    __shared__ float Bv[CH * NST];
    const int tid = threadIdx.x;
    const int dloc = tid >> 1;
    const int d0 = blockIdx.x * 128;
    const int nb = (tid & 1) * 8;
    const int c = blockIdx.y;
    const int b = blockIdx.z;

    const size_t rowbase = (size_t)(b * TT + c * CH) * DD + d0;
#pragma unroll
    for (int i = 0; i < 4; i++) {
        int lin = tid + i * 256;                // 1024 float4
        int t = lin >> 5, q = lin & 31;
        *reinterpret_cast<float4*>(&sdt[t][q * 4]) =
            *reinterpret_cast<const float4*>(g_dt + rowbase + (size_t)t * DD + q * 4);
        *reinterpret_cast<float4*>(&sx[t][q * 4]) =
            *reinterpret_cast<const float4*>(x + rowbase + (size_t)t * DD + q * 4);
    }
#pragma unroll
    for (int i = 0; i < 2; i++) {               // CH*NST = 512 Bv entries
        int lin = tid + i * 256;
        int t = lin >> 4, n = lin & 15;
        float A = -ex2(logA[n] * LOG2E);
        Bv[lin] = g_proj[(size_t)(b * TT + c * CH + t) * PCOLS + n] * rcpa(A + 1e-8f);
    }

    float An2[8], h[8];
#pragma unroll
    for (int j = 0; j < 8; j++) {
        An2[j] = -ex2(logA[nb + j] * LOG2E) * LOG2E;
        h[j] = 0.0f;
    }
    __syncthreads();

    float sumdt = 0.0f;
#pragma unroll
    for (int t = 0; t < CH; t++) {
        float dtv = sdt[t][dloc];
        float xv = sx[t][dloc];
        sumdt += dtv;
        float4 b0 = *reinterpret_cast<const float4*>(&Bv[t * NST + nb]);
        float4 b1 = *reinterpret_cast<const float4*>(&Bv[t * NST + nb + 4]);
        float bv[8] = {b0.x, b0.y, b0.z, b0.w, b1.x, b1.y, b1.z, b1.w};
#pragma unroll
        for (int j = 0; j < 8; j++) {
            float a = ex2(dtv * An2[j]);
            float g = xv * bv[j];
            h[j] = fmaf(a, h[j] + g, -g);
        }
    }

    const int d = d0 + dloc;
    size_t base = (((size_t)b * NC + c) * DD + d) * NST + nb;
    float4 P0 = {ex2(An2[0] * sumdt), ex2(An2[1] * sumdt),
                 ex2(An2[2] * sumdt), ex2(An2[3] * sumdt)};
    float4 P1 = {ex2(An2[4] * sumdt), ex2(An2[5] * sumdt),
                 ex2(An2[6] * sumdt), ex2(An2[7] * sumdt)};
    *reinterpret_cast<float4*>(g_P + base)     = P0;
    *reinterpret_cast<float4*>(g_P + base + 4) = P1;
    float4 H0 = {h[0], h[1], h[2], h[3]};
    float4 H1 = {h[4], h[5], h[6], h[7]};
    *reinterpret_cast<float4*>(g_H + base)     = H0;
    *reinterpret_cast<float4*>(g_H + base + 4) = H1;
}

// ---------------- kernel 4: combine chunks ---------------------------------
__global__ __launch_bounds__(256) void combine() {
    int idx = blockIdx.x * 256 + threadIdx.x;
    int b = idx / (DD * NST);
    int rem = idx - b * (DD * NST);
    float run = 0.0f;
#pragma unroll 16
    for (int c = 0; c < NC; c++) {
        size_t off = ((size_t)b * NC + c) * (DD * NST) + rem;
        float P = g_P[off];
        float H = g_H[off];
        float nw = fmaf(P, run, H);
        g_H[off] = run;
        run = nw;
    }
}

// ---------------- kernel 5: pass 2 — re-scan with correct init, emit y -----
__global__ __launch_bounds__(256, 4) void scan_pass2(const float* __restrict__ x,
                                                     const float* __restrict__ logA,
                                                     const float* __restrict__ Dskip,
                                                     float* __restrict__ out) {
    __shared__ float sdt[CH][128];
    __shared__ float sx[CH][128];
    __shared__ float sy[CH][128];
    __shared__ float Bv[CH * NST];
    __shared__ float Cs[CH * NST];
    const int tid = threadIdx.x;
    const int dloc = tid >> 1;
    const int d0 = blockIdx.x * 128;
    const int nh = tid & 1;
    const int nb = nh * 8;
    const int c = blockIdx.y;
    const int b = blockIdx.z;

    const size_t rowbase = (size_t)(b * TT + c * CH) * DD + d0;
#pragma unroll
    for (int i = 0; i < 4; i++) {
        int lin = tid + i * 256;
        int t = lin >> 5, q = lin & 31;
        *reinterpret_cast<float4*>(&sdt[t][q * 4]) =
            *reinterpret_cast<const float4*>(g_dt + rowbase + (size_t)t * DD + q * 4);
        *reinterpret_cast<float4*>(&sx[t][q * 4]) =
            *reinterpret_cast<const float4*>(x + rowbase + (size_t)t * DD + q * 4);
    }
#pragma unroll
    for (int i = 0; i < 2; i++) {
        int lin = tid + i * 256;
        int t = lin >> 4, n = lin & 15;
        float A = -ex2(logA[n] * LOG2E);
        size_t prow = (size_t)(b * TT + c * CH + t) * PCOLS;
        Bv[lin] = g_proj[prow + n] * rcpa(A + 1e-8f);
        Cs[lin] = g_proj[prow + 16 + n];
    }

    const int d = d0 + dloc;
    float An2[8], h[8];
    size_t base = (((size_t)b * NC + c) * DD + d) * NST + nb;
    float4 H0 = *reinterpret_cast<const float4*>(g_H + base);
    float4 H1 = *reinterpret_cast<const float4*>(g_H + base + 4);
    h[0] = H0.x; h[1] = H0.y; h[2] = H0.z; h[3] = H0.w;
    h[4] = H1.x; h[5] = H1.y; h[6] = H1.z; h[7] = H1.w;
#pragma unroll
    for (int j = 0; j < 8; j++)
        An2[j] = -ex2(logA[nb + j] * LOG2E) * LOG2E;
    const float dsk = Dskip[d];
    __syncthreads();

#pragma unroll
    for (int t = 0; t < CH; t++) {
        float dtv = sdt[t][dloc];
        float xv = sx[t][dloc];
        float4 b0 = *reinterpret_cast<const float4*>(&Bv[t * NST + nb]);
        float4 b1 = *reinterpret_cast<const float4*>(&Bv[t * NST + nb + 4]);
        float bv[8] = {b0.x, b0.y, b0.z, b0.w, b1.x, b1.y, b1.z, b1.w};
        float4 c0 = *reinterpret_cast<const float4*>(&Cs[t * NST + nb]);
        float4 c1 = *reinterpret_cast<const float4*>(&Cs[t * NST + nb + 4]);
        float cv[8] = {c0.x, c0.y, c0.z, c0.w, c1.x, c1.y, c1.z, c1.w};
        float y = 0.0f;
#pragma unroll
        for (int j = 0; j < 8; j++) {
            float a = ex2(dtv * An2[j]);
            float g = xv * bv[j];
            h[j] = fmaf(a, h[j] + g, -g);
            y = fmaf(h[j], cv[j], y);
        }
        y += __shfl_xor_sync(0xffffffffu, y, 1);
        if (nh == 0) sy[t][dloc] = fmaf(dsk, xv, y);
    }
    __syncthreads();

#pragma unroll
    for (int i = 0; i < 4; i++) {
        int lin = tid + i * 256;
        int t = lin >> 5, q = lin & 31;
        *reinterpret_cast<float4*>(out + rowbase + (size_t)t * DD + q * 4) =
            *reinterpret_cast<const float4*>(&sy[t][q * 4]);
    }
}

// ---------------- launcher -------------------------------------------------
extern "C" void kernel_launch(void* const* d_in, const int* in_sizes, int n_in,
                              void* d_out, int out_size) {
    const float* x    = (const float*)d_in[0];
    const float* WB   = (const float*)d_in[1];
    const float* WC   = (const float*)d_in[2];
    const float* Wdt1 = (const float*)d_in[3];
    const float* Wdt2 = (const float*)d_in[4];
    const float* bdt2 = (const float*)d_in[5];
    const float* logA = (const float*)d_in[6];
    const float* Dsk  = (const float*)d_in[7];
    float* out = (float*)d_out;

    proj_mma<<<dim3(BT / 128, KSPLIT), 256>>>(x, WB, WC, Wdt1);
    reduce_proj<<<(BT * PCOLS / 4 + 255) / 256, 256>>>();
    dt_mma<<<dim3(BT / 128, DD / 128), 256>>>(Wdt2, bdt2);
    scan_pass1<<<dim3(DD / 128, NC, BSZ), 256>>>(x, logA);
    combine<<<(BSZ * DD * NST) / 256, 256>>>();
    scan_pass2<<<dim3(DD / 128, NC, BSZ), 256>>>(x, logA, Dsk, out);
}

// round 13
// speedup vs baseline: 1.7880x; 1.0432x over previous
#include <cuda_runtime.h>
#include <cuda_bf16.h>
#include <math.h>

#define BSZ 2
#define TT 2048
#define DD 1024
#define NST 16
#define RK 64
#define BT (BSZ*TT)          // 4096
#define NC 64                // chunks
#define CH (TT/NC)           // 32 steps per chunk
#define PCOLS 96             // 16 B + 16 C + 64 R
#define KSPLIT 8
#define LOG2E 1.44269504f

__device__ __forceinline__ float ex2(float v) {
    float r; asm("ex2.approx.f32 %0, %1;" : "=f"(r) : "f"(v)); return r;
}
__device__ __forceinline__ float rcpa(float v) {
    float r; asm("rcp.approx.f32 %0, %1;" : "=f"(r) : "f"(v)); return r;
}

// ---------------- scratch (static device memory; no allocs allowed) --------
__device__ float g_part[KSPLIT * BT * PCOLS]; // split-K partials
__device__ float g_proj[BT * PCOLS];          // col 0-15 = B_t, 16-31 = C_t, 32-95 = R
__device__ float g_dt[BT * DD];               // softplus(dt_raw)
__device__ float g_P[BSZ * NC * DD * NST];    // per-chunk product of a_t
__device__ float g_H[BSZ * NC * DD * NST];    // chunk-local final h -> becomes init h

// split one float4 into two packed bf16x4 (hi, lo)
__device__ __forceinline__ void split4(float4 v, uint2& hw, uint2& lw) {
    float f[4] = {v.x, v.y, v.z, v.w};
    unsigned h[2], l[2];
#pragma unroll
    for (int k = 0; k < 2; k++) {
        __nv_bfloat16 h0 = __float2bfloat16(f[2 * k]);
        __nv_bfloat16 h1 = __float2bfloat16(f[2 * k + 1]);
        __nv_bfloat16 l0 = __float2bfloat16(f[2 * k] - __bfloat162float(h0));
        __nv_bfloat16 l1 = __float2bfloat16(f[2 * k + 1] - __bfloat162float(h1));
        h[k] = (unsigned)__bfloat16_as_ushort(h0) | ((unsigned)__bfloat16_as_ushort(h1) << 16);
        l[k] = (unsigned)__bfloat16_as_ushort(l0) | ((unsigned)__bfloat16_as_ushort(l1) << 16);
    }
    hw = make_uint2(h[0], h[1]);
    lw = make_uint2(l[0], l[1]);
}

__device__ __forceinline__ void mma_bf16(float* d, const unsigned* a,
                                         unsigned b0, unsigned b1) {
    asm("mma.sync.aligned.m16n8k16.row.col.f32.bf16.bf16.f32 "
        "{%0,%1,%2,%3}, {%4,%5,%6,%7}, {%8,%9}, {%0,%1,%2,%3};"
        : "+f"(d[0]), "+f"(d[1]), "+f"(d[2]), "+f"(d[3])
        : "r"(a[0]), "r"(a[1]), "r"(a[2]), "r"(a[3]), "r"(b0), "r"(b1));
}

// ---------------- kernel 1: proj GEMM via tensor cores ---------------------
// grid (BT/128, KSPLIT=8), block 256. 128 K per block (4 k-tiles of 32).
// Register-staged prefetch: next tile's LDG overlaps current tile's MMAs.
__global__ __launch_bounds__(256) void proj_mma(const float* __restrict__ x,
                                                const float* __restrict__ WB,
                                                const float* __restrict__ WC,
                                                const float* __restrict__ Wdt1) {
    __shared__ __nv_bfloat16 Ahi[128][40];
    __shared__ __nv_bfloat16 Alo[128][40];
    __shared__ __nv_bfloat16 Bhi[96][40];
    __shared__ __nv_bfloat16 Blo[96][40];
    const int tid = threadIdx.x;
    const int lane = tid & 31, wid = tid >> 5;
    const int warpM = wid & 3;              // 4 x 32 rows
    const int warpN = wid >> 2;             // 2 x 48 cols
    const int row0 = blockIdx.x * 128;
    const int kb = blockIdx.y * (DD / KSPLIT);   // 128 K columns per block

    float4 xr[4];
    float4 wr[3];
    const int bn = tid >> 3, bq = tid & 7;  // B-tile coords (threads 0..767 via i*256)

    auto ldg_tile = [&](int kcur) {
#pragma unroll
        for (int i = 0; i < 4; i++) {
            int lin = tid + i * 256;
            int r = lin >> 3, q = lin & 7;
            xr[i] = *reinterpret_cast<const float4*>(
                x + (size_t)(row0 + r) * DD + kcur + q * 4);
        }
#pragma unroll
        for (int i = 0; i < 3; i++) {
            int lin = tid + i * 256;
            if (lin < 768) {
                int n = lin >> 3;
                const float* src = (n < 16) ? (WB + (size_t)n * DD)
                                  : (n < 32) ? (WC + (size_t)(n - 16) * DD)
                                             : (Wdt1 + (size_t)(n - 32) * DD);
                wr[i] = *reinterpret_cast<const float4*>(src + kcur + bq * 4);
            }
        }
    };
    auto sts_tile = [&]() {
#pragma unroll
        for (int i = 0; i < 4; i++) {
            int lin = tid + i * 256;
            int r = lin >> 3, q = lin & 7;
            uint2 hw, lw;
            split4(xr[i], hw, lw);
            *reinterpret_cast<uint2*>(&Ahi[r][q * 4]) = hw;
            *reinterpret_cast<uint2*>(&Alo[r][q * 4]) = lw;
        }
#pragma unroll
        for (int i = 0; i < 3; i++) {
            int lin = tid + i * 256;
            if (lin < 768) {
                int n = lin >> 3;
                uint2 hw, lw;
                split4(wr[i], hw, lw);
                *reinterpret_cast<uint2*>(&Bhi[n][bq * 4]) = hw;
                *reinterpret_cast<uint2*>(&Blo[n][bq * 4]) = lw;
            }
        }
    };

    float acc[2][6][4];
#pragma unroll
    for (int mt = 0; mt < 2; mt++)
#pragma unroll
        for (int nt = 0; nt < 6; nt++)
#pragma unroll
            for (int q = 0; q < 4; q++) acc[mt][nt][q] = 0.0f;

    ldg_tile(kb);
#pragma unroll 1
    for (int kt = 0; kt < 4; kt++) {
        sts_tile();
        __syncthreads();
        if (kt < 3) ldg_tile(kb + (kt + 1) * 32);   // overlaps MMA below

#pragma unroll
        for (int seg = 0; seg < 3; seg++) {
            const __nv_bfloat16 (*Asp)[40] = (seg < 2) ? Ahi : Alo;
            const __nv_bfloat16 (*Bsp)[40] = (seg == 1) ? Blo : Bhi;
#pragma unroll
            for (int k16 = 0; k16 < 32; k16 += 16) {
                const int ccol = k16 + (lane & 3) * 2;
                unsigned a[2][4];
#pragma unroll
                for (int mt = 0; mt < 2; mt++) {
                    int r = warpM * 32 + mt * 16 + (lane >> 2);
                    a[mt][0] = *reinterpret_cast<const unsigned*>(&Asp[r][ccol]);
                    a[mt][1] = *reinterpret_cast<const unsigned*>(&Asp[r + 8][ccol]);
                    a[mt][2] = *reinterpret_cast<const unsigned*>(&Asp[r][ccol + 8]);
                    a[mt][3] = *reinterpret_cast<const unsigned*>(&Asp[r + 8][ccol + 8]);
                }
#pragma unroll
                for (int nt = 0; nt < 6; nt++) {
                    int n = warpN * 48 + nt * 8 + (lane >> 2);
                    unsigned b0 = *reinterpret_cast<const unsigned*>(&Bsp[n][ccol]);
                    unsigned b1 = *reinterpret_cast<const unsigned*>(&Bsp[n][ccol + 8]);
                    mma_bf16(acc[0][nt], a[0], b0, b1);
                    mma_bf16(acc[1][nt], a[1], b0, b1);
                }
            }
        }
        __syncthreads();
    }

    float* outp = g_part + (size_t)blockIdx.y * BT * PCOLS;
#pragma unroll
    for (int mt = 0; mt < 2; mt++)
#pragma unroll
        for (int nt = 0; nt < 6; nt++) {
            int r = row0 + warpM * 32 + mt * 16 + (lane >> 2);
            int c = warpN * 48 + nt * 8 + (lane & 3) * 2;
            float2 v0 = {acc[mt][nt][0], acc[mt][nt][1]};
            float2 v1 = {acc[mt][nt][2], acc[mt][nt][3]};
            *reinterpret_cast<float2*>(&outp[(size_t)r * PCOLS + c]) = v0;
            *reinterpret_cast<float2*>(&outp[(size_t)(r + 8) * PCOLS + c]) = v1;
        }
}

// ---------------- kernel 1b: reduce split-K partials (float4) --------------
__global__ __launch_bounds__(256) void reduce_proj() {
    int i = blockIdx.x * 256 + threadIdx.x;     // float4 index
    if (i < BT * PCOLS / 4) {
        float4 s = {0.f, 0.f, 0.f, 0.f};
#pragma unroll
        for (int k = 0; k < KSPLIT; k++) {
            float4 v = reinterpret_cast<const float4*>(g_part)[(size_t)k * (BT * PCOLS / 4) + i];
            s.x += v.x; s.y += v.y; s.z += v.z; s.w += v.w;
        }
        reinterpret_cast<float4*>(g_proj)[i] = s;
    }
}

// ---------------- kernel 2: dt GEMM via tensor cores (resident smem) -------
__global__ __launch_bounds__(256) void dt_mma(const float* __restrict__ W2,
                                              const float* __restrict__ bdt) {
    __shared__ __nv_bfloat16 Ahi[128][72];
    __shared__ __nv_bfloat16 Alo[128][72];
    __shared__ __nv_bfloat16 Bhi[128][72];
    __shared__ __nv_bfloat16 Blo[128][72];
    const int tid = threadIdx.x;
    const int lane = tid & 31, wid = tid >> 5;
    const int warpM = wid & 3;              // 4 x 32 rows
    const int warpN = wid >> 2;             // 2 x 64 cols
    const int row0 = blockIdx.x * 128;
    const int col0 = blockIdx.y * 128;

#pragma unroll
    for (int i = 0; i < 8; i++) {
        int lin = tid + i * 256;                // 2048 float4
        int r = lin >> 4, q = lin & 15;
        float4 v = *reinterpret_cast<const float4*>(
            g_proj + (size_t)(row0 + r) * PCOLS + 32 + q * 4);
        uint2 hw, lw;
        split4(v, hw, lw);
        *reinterpret_cast<uint2*>(&Ahi[r][q * 4]) = hw;
        *reinterpret_cast<uint2*>(&Alo[r][q * 4]) = lw;
    }
#pragma unroll
    for (int i = 0; i < 8; i++) {
        int lin = tid + i * 256;
        int n = lin >> 4, q = lin & 15;
        float4 v = *reinterpret_cast<const float4*>(
            W2 + (size_t)(col0 + n) * RK + q * 4);
        uint2 hw, lw;
        split4(v, hw, lw);
        *reinterpret_cast<uint2*>(&Bhi[n][q * 4]) = hw;
        *reinterpret_cast<uint2*>(&Blo[n][q * 4]) = lw;
    }
    __syncthreads();

    float acc[2][8][4];
#pragma unroll
    for (int mt = 0; mt < 2; mt++)
#pragma unroll
        for (int nt = 0; nt < 8; nt++)
#pragma unroll
            for (int q = 0; q < 4; q++) acc[mt][nt][q] = 0.0f;

#pragma unroll
    for (int seg = 0; seg < 3; seg++) {
        const __nv_bfloat16 (*Asp)[72] = (seg < 2) ? Ahi : Alo;
        const __nv_bfloat16 (*Bsp)[72] = (seg == 1) ? Blo : Bhi;
#pragma unroll
        for (int k16 = 0; k16 < 64; k16 += 16) {
            const int ccol = k16 + (lane & 3) * 2;
            unsigned a[2][4];
#pragma unroll
            for (int mt = 0; mt < 2; mt++) {
                int r = warpM * 32 + mt * 16 + (lane >> 2);
                a[mt][0] = *reinterpret_cast<const unsigned*>(&Asp[r][ccol]);
                a[mt][1] = *reinterpret_cast<const unsigned*>(&Asp[r + 8][ccol]);
                a[mt][2] = *reinterpret_cast<const unsigned*>(&Asp[r][ccol + 8]);
                a[mt][3] = *reinterpret_cast<const unsigned*>(&Asp[r + 8][ccol + 8]);
            }
#pragma unroll
            for (int nt = 0; nt < 8; nt++) {
                int n = warpN * 64 + nt * 8 + (lane >> 2);
                unsigned b0 = *reinterpret_cast<const unsigned*>(&Bsp[n][ccol]);
                unsigned b1 = *reinterpret_cast<const unsigned*>(&Bsp[n][ccol + 8]);
                mma_bf16(acc[0][nt], a[0], b0, b1);
                mma_bf16(acc[1][nt], a[1], b0, b1);
            }
        }
    }

#pragma unroll
    for (int mt = 0; mt < 2; mt++)
#pragma unroll
        for (int nt = 0; nt < 8; nt++) {
            int r = row0 + warpM * 32 + mt * 16 + (lane >> 2);
            int c = col0 + warpN * 64 + nt * 8 + (lane & 3) * 2;
            float b0 = bdt[c], b1 = bdt[c + 1];
            float v0 = acc[mt][nt][0] + b0;
            float v1 = acc[mt][nt][1] + b1;
            float v2 = acc[mt][nt][2] + b0;
            float v3 = acc[mt][nt][3] + b1;
            float2 r0 = {(v0 > 20.0f) ? v0 : log1pf(__expf(v0)),
                         (v1 > 20.0f) ? v1 : log1pf(__expf(v1))};
            float2 r1 = {(v2 > 20.0f) ? v2 : log1pf(__expf(v2)),
                         (v3 > 20.0f) ? v3 : log1pf(__expf(v3))};
            *reinterpret_cast<float2*>(&g_dt[(size_t)r * DD + c]) = r0;
            *reinterpret_cast<float2*>(&g_dt[(size_t)(r + 8) * DD + c]) = r1;
        }
}

// ---------------- kernel 3: pass 1 — per-chunk local scan (CH=32) ----------
__global__ __launch_bounds__(256, 6) void scan_pass1(const float* __restrict__ x,
                                                     const float* __restrict__ logA) {
    __shared__ float sdt[CH][128];
    __shared__ float sx[CH][128];
    __shared__ float Bv[CH * NST];
    const int tid = threadIdx.x;
    const int dloc = tid >> 1;
    const int d0 = blockIdx.x * 128;
    const int nb = (tid & 1) * 8;
    const int c = blockIdx.y;
    const int b = blockIdx.z;

    const size_t rowbase = (size_t)(b * TT + c * CH) * DD + d0;
#pragma unroll
    for (int i = 0; i < 4; i++) {
        int lin = tid + i * 256;                // 1024 float4
        int t = lin >> 5, q = lin & 31;
        *reinterpret_cast<float4*>(&sdt[t][q * 4]) =
            *reinterpret_cast<const float4*>(g_dt + rowbase + (size_t)t * DD + q * 4);
        *reinterpret_cast<float4*>(&sx[t][q * 4]) =
            *reinterpret_cast<const float4*>(x + rowbase + (size_t)t * DD + q * 4);
    }
#pragma unroll
    for (int i = 0; i < 2; i++) {               // CH*NST = 512 Bv entries
        int lin = tid + i * 256;
        int t = lin >> 4, n = lin & 15;
        float A = -ex2(logA[n] * LOG2E);
        Bv[lin] = g_proj[(size_t)(b * TT + c * CH + t) * PCOLS + n] * rcpa(A + 1e-8f);
    }

    float An2[8], h[8];
#pragma unroll
    for (int j = 0; j < 8; j++) {
        An2[j] = -ex2(logA[nb + j] * LOG2E) * LOG2E;
        h[j] = 0.0f;
    }
    __syncthreads();

    float sumdt = 0.0f;
#pragma unroll
    for (int t = 0; t < CH; t++) {
        float dtv = sdt[t][dloc];
        float xv = sx[t][dloc];
        sumdt += dtv;
        float4 b0 = *reinterpret_cast<const float4*>(&Bv[t * NST + nb]);
        float4 b1 = *reinterpret_cast<const float4*>(&Bv[t * NST + nb + 4]);
        float bv[8] = {b0.x, b0.y, b0.z, b0.w, b1.x, b1.y, b1.z, b1.w};
#pragma unroll
        for (int j = 0; j < 8; j++) {
            float a = ex2(dtv * An2[j]);
            float g = xv * bv[j];
            h[j] = fmaf(a, h[j] + g, -g);
        }
    }

    const int d = d0 + dloc;
    size_t base = (((size_t)b * NC + c) * DD + d) * NST + nb;
    float4 P0 = {ex2(An2[0] * sumdt), ex2(An2[1] * sumdt),
                 ex2(An2[2] * sumdt), ex2(An2[3] * sumdt)};
    float4 P1 = {ex2(An2[4] * sumdt), ex2(An2[5] * sumdt),
                 ex2(An2[6] * sumdt), ex2(An2[7] * sumdt)};
    *reinterpret_cast<float4*>(g_P + base)     = P0;
    *reinterpret_cast<float4*>(g_P + base + 4) = P1;
    float4 H0 = {h[0], h[1], h[2], h[3]};
    float4 H1 = {h[4], h[5], h[6], h[7]};
    *reinterpret_cast<float4*>(g_H + base)     = H0;
    *reinterpret_cast<float4*>(g_H + base + 4) = H1;
}

// ---------------- kernel 4: combine chunks ---------------------------------
__global__ __launch_bounds__(256) void combine() {
    int idx = blockIdx.x * 256 + threadIdx.x;
    int b = idx / (DD * NST);
    int rem = idx - b * (DD * NST);
    float run = 0.0f;
#pragma unroll 16
    for (int c = 0; c < NC; c++) {
        size_t off = ((size_t)b * NC + c) * (DD * NST) + rem;
        float P = g_P[off];
        float H = g_H[off];
        float nw = fmaf(P, run, H);
        g_H[off] = run;
        run = nw;
    }
}

// ---------------- kernel 5: pass 2 — re-scan with correct init, emit y -----
// sy is ALIASED onto sdt: sdt[t][dloc] is read by the owning lane pair
// strictly before the nh==0 lane writes sy[t][dloc] (same warp, program
// order), and no other thread touches that column during the loop.
__global__ __launch_bounds__(256, 5) void scan_pass2(const float* __restrict__ x,
                                                     const float* __restrict__ logA,
                                                     const float* __restrict__ Dskip,
                                                     float* __restrict__ out) {
    __shared__ float sdt[CH][128];
    __shared__ float sx[CH][128];
    __shared__ float Bv[CH * NST];
    __shared__ float Cs[CH * NST];
    float (*sy)[128] = sdt;                  // alias (see note above)
    const int tid = threadIdx.x;
    const int dloc = tid >> 1;
    const int d0 = blockIdx.x * 128;
    const int nh = tid & 1;
    const int nb = nh * 8;
    const int c = blockIdx.y;
    const int b = blockIdx.z;

    const size_t rowbase = (size_t)(b * TT + c * CH) * DD + d0;
#pragma unroll
    for (int i = 0; i < 4; i++) {
        int lin = tid + i * 256;
        int t = lin >> 5, q = lin & 31;
        *reinterpret_cast<float4*>(&sdt[t][q * 4]) =
            *reinterpret_cast<const float4*>(g_dt + rowbase + (size_t)t * DD + q * 4);
        *reinterpret_cast<float4*>(&sx[t][q * 4]) =
            *reinterpret_cast<const float4*>(x + rowbase + (size_t)t * DD + q * 4);
    }
#pragma unroll
    for (int i = 0; i < 2; i++) {
        int lin = tid + i * 256;
        int t = lin >> 4, n = lin & 15;
        float A = -ex2(logA[n] * LOG2E);
        size_t prow = (size_t)(b * TT + c * CH + t) * PCOLS;
        Bv[lin] = g_proj[prow + n] * rcpa(A + 1e-8f);
        Cs[lin] = g_proj[prow + 16 + n];
    }

    const int d = d0 + dloc;
    float An2[8], h[8];
    size_t base = (((size_t)b * NC + c) * DD + d) * NST + nb;
    float4 H0 = *reinterpret_cast<const float4*>(g_H + base);
    float4 H1 = *reinterpret_cast<const float4*>(g_H + base + 4);
    h[0] = H0.x; h[1] = H0.y; h[2] = H0.z; h[3] = H0.w;
    h[4] = H1.x; h[5] = H1.y; h[6] = H1.z; h[7] = H1.w;
#pragma unroll
    for (int j = 0; j < 8; j++)
        An2[j] = -ex2(logA[nb + j] * LOG2E) * LOG2E;
    const float dsk = Dskip[d];
    __syncthreads();

#pragma unroll
    for (int t = 0; t < CH; t++) {
        float dtv = sdt[t][dloc];
        float xv = sx[t][dloc];
        float4 b0 = *reinterpret_cast<const float4*>(&Bv[t * NST + nb]);
        float4 b1 = *reinterpret_cast<const float4*>(&Bv[t * NST + nb + 4]);
        float bv[8] = {b0.x, b0.y, b0.z, b0.w, b1.x, b1.y, b1.z, b1.w};
        float4 c0 = *reinterpret_cast<const float4*>(&Cs[t * NST + nb]);
        float4 c1 = *reinterpret_cast<const float4*>(&Cs[t * NST + nb + 4]);
        float cv[8] = {c0.x, c0.y, c0.z, c0.w, c1.x, c1.y, c1.z, c1.w};
        float y = 0.0f;
#pragma unroll
        for (int j = 0; j < 8; j++) {
            float a = ex2(dtv * An2[j]);
            float g = xv * bv[j];
            h[j] = fmaf(a, h[j] + g, -g);
            y = fmaf(h[j], cv[j], y);
        }
        y += __shfl_xor_sync(0xffffffffu, y, 1);
        if (nh == 0) sy[t][dloc] = fmaf(dsk, xv, y);
    }
    __syncthreads();

#pragma unroll
    for (int i = 0; i < 4; i++) {
        int lin = tid + i * 256;
        int t = lin >> 5, q = lin & 31;
        *reinterpret_cast<float4*>(out + rowbase + (size_t)t * DD + q * 4) =
            *reinterpret_cast<const float4*>(&sy[t][q * 4]);
    }
}

// ---------------- launcher -------------------------------------------------
extern "C" void kernel_launch(void* const* d_in, const int* in_sizes, int n_in,
                              void* d_out, int out_size) {
    const float* x    = (const float*)d_in[0];
    const float* WB   = (const float*)d_in[1];
    const float* WC   = (const float*)d_in[2];
    const float* Wdt1 = (const float*)d_in[3];
    const float* Wdt2 = (const float*)d_in[4];
    const float* bdt2 = (const float*)d_in[5];
    const float* logA = (const float*)d_in[6];
    const float* Dsk  = (const float*)d_in[7];
    float* out = (float*)d_out;

    proj_mma<<<dim3(BT / 128, KSPLIT), 256>>>(x, WB, WC, Wdt1);
    reduce_proj<<<(BT * PCOLS / 4 + 255) / 256, 256>>>();
    dt_mma<<<dim3(BT / 128, DD / 128), 256>>>(Wdt2, bdt2);
    scan_pass1<<<dim3(DD / 128, NC, BSZ), 256>>>(x, logA);
    combine<<<(BSZ * DD * NST) / 256, 256>>>();
    scan_pass2<<<dim3(DD / 128, NC, BSZ), 256>>>(x, logA, Dsk, out);
}

// round 14
// speedup vs baseline: 1.8141x; 1.0146x over previous
#include <cuda_runtime.h>
#include <cuda_bf16.h>
#include <math.h>

#define BSZ 2
#define TT 2048
#define DD 1024
#define NST 16
#define RK 64
#define BT (BSZ*TT)          // 4096
#define NC 64                // chunks
#define CH (TT/NC)           // 32 steps per chunk
#define PCOLS 96             // 16 B + 16 C + 64 R
#define KSPLIT 4
#define LOG2E 1.44269504f

__device__ __forceinline__ float ex2(float v) {
    float r; asm("ex2.approx.f32 %0, %1;" : "=f"(r) : "f"(v)); return r;
}
__device__ __forceinline__ float rcpa(float v) {
    float r; asm("rcp.approx.f32 %0, %1;" : "=f"(r) : "f"(v)); return r;
}

// ---------------- scratch (static device memory; no allocs allowed) --------
__device__ float g_part[KSPLIT * BT * PCOLS]; // split-K partials
__device__ float g_proj[BT * PCOLS];          // col 0-15 = B_t, 16-31 = C_t, 32-95 = R
__device__ float g_dt[BT * DD];               // softplus(dt_raw)
__device__ float g_S[BSZ * NC * DD];          // per-chunk sum of dt  (replaces g_P)
__device__ float g_H[BSZ * NC * DD * NST];    // chunk-local final h -> becomes init h

// split one float4 into two packed bf16x4 (hi, lo)
__device__ __forceinline__ void split4(float4 v, uint2& hw, uint2& lw) {
    float f[4] = {v.x, v.y, v.z, v.w};
    unsigned h[2], l[2];
#pragma unroll
    for (int k = 0; k < 2; k++) {
        __nv_bfloat16 h0 = __float2bfloat16(f[2 * k]);
        __nv_bfloat16 h1 = __float2bfloat16(f[2 * k + 1]);
        __nv_bfloat16 l0 = __float2bfloat16(f[2 * k] - __bfloat162float(h0));
        __nv_bfloat16 l1 = __float2bfloat16(f[2 * k + 1] - __bfloat162float(h1));
        h[k] = (unsigned)__bfloat16_as_ushort(h0) | ((unsigned)__bfloat16_as_ushort(h1) << 16);
        l[k] = (unsigned)__bfloat16_as_ushort(l0) | ((unsigned)__bfloat16_as_ushort(l1) << 16);
    }
    hw = make_uint2(h[0], h[1]);
    lw = make_uint2(l[0], l[1]);
}

__device__ __forceinline__ void mma_bf16(float* d, const unsigned* a,
                                         unsigned b0, unsigned b1) {
    asm("mma.sync.aligned.m16n8k16.row.col.f32.bf16.bf16.f32 "
        "{%0,%1,%2,%3}, {%4,%5,%6,%7}, {%8,%9}, {%0,%1,%2,%3};"
        : "+f"(d[0]), "+f"(d[1]), "+f"(d[2]), "+f"(d[3])
        : "r"(a[0]), "r"(a[1]), "r"(a[2]), "r"(a[3]), "r"(b0), "r"(b1));
}

// ---------------- kernel 1: proj GEMM via tensor cores ---------------------
// grid (BT/128, KSPLIT=4), block 256. 256 K per block (8 k-tiles of 32).
// Register-staged prefetch: next tile's LDG overlaps current tile's MMAs.
__global__ __launch_bounds__(256) void proj_mma(const float* __restrict__ x,
                                                const float* __restrict__ WB,
                                                const float* __restrict__ WC,
                                                const float* __restrict__ Wdt1) {
    __shared__ __nv_bfloat16 Ahi[128][40];
    __shared__ __nv_bfloat16 Alo[128][40];
    __shared__ __nv_bfloat16 Bhi[96][40];
    __shared__ __nv_bfloat16 Blo[96][40];
    const int tid = threadIdx.x;
    const int lane = tid & 31, wid = tid >> 5;
    const int warpM = wid & 3;              // 4 x 32 rows
    const int warpN = wid >> 2;             // 2 x 48 cols
    const int row0 = blockIdx.x * 128;
    const int kb = blockIdx.y * (DD / KSPLIT);   // 256 K columns per block

    float4 xr[4];
    float4 wr[3];
    const int bq = tid & 7;

    auto ldg_tile = [&](int kcur) {
#pragma unroll
        for (int i = 0; i < 4; i++) {
            int lin = tid + i * 256;
            int r = lin >> 3, q = lin & 7;
            xr[i] = *reinterpret_cast<const float4*>(
                x + (size_t)(row0 + r) * DD + kcur + q * 4);
        }
#pragma unroll
        for (int i = 0; i < 3; i++) {
            int lin = tid + i * 256;
            if (lin < 768) {
                int n = lin >> 3;
                const float* src = (n < 16) ? (WB + (size_t)n * DD)
                                  : (n < 32) ? (WC + (size_t)(n - 16) * DD)
                                             : (Wdt1 + (size_t)(n - 32) * DD);
                wr[i] = *reinterpret_cast<const float4*>(src + kcur + bq * 4);
            }
        }
    };
    auto sts_tile = [&]() {
#pragma unroll
        for (int i = 0; i < 4; i++) {
            int lin = tid + i * 256;
            int r = lin >> 3, q = lin & 7;
            uint2 hw, lw;
            split4(xr[i], hw, lw);
            *reinterpret_cast<uint2*>(&Ahi[r][q * 4]) = hw;
            *reinterpret_cast<uint2*>(&Alo[r][q * 4]) = lw;
        }
#pragma unroll
        for (int i = 0; i < 3; i++) {
            int lin = tid + i * 256;
            if (lin < 768) {
                int n = lin >> 3;
                uint2 hw, lw;
                split4(wr[i], hw, lw);
                *reinterpret_cast<uint2*>(&Bhi[n][bq * 4]) = hw;
                *reinterpret_cast<uint2*>(&Blo[n][bq * 4]) = lw;
            }
        }
    };

    float acc[2][6][4];
#pragma unroll
    for (int mt = 0; mt < 2; mt++)
#pragma unroll
        for (int nt = 0; nt < 6; nt++)
#pragma unroll
            for (int q = 0; q < 4; q++) acc[mt][nt][q] = 0.0f;

    ldg_tile(kb);
#pragma unroll 1
    for (int kt = 0; kt < 8; kt++) {
        sts_tile();
        __syncthreads();
        if (kt < 7) ldg_tile(kb + (kt + 1) * 32);   // overlaps MMA below

#pragma unroll
        for (int seg = 0; seg < 3; seg++) {
            const __nv_bfloat16 (*Asp)[40] = (seg < 2) ? Ahi : Alo;
            const __nv_bfloat16 (*Bsp)[40] = (seg == 1) ? Blo : Bhi;
#pragma unroll
            for (int k16 = 0; k16 < 32; k16 += 16) {
                const int ccol = k16 + (lane & 3) * 2;
                unsigned a[2][4];
#pragma unroll
                for (int mt = 0; mt < 2; mt++) {
                    int r = warpM * 32 + mt * 16 + (lane >> 2);
                    a[mt][0] = *reinterpret_cast<const unsigned*>(&Asp[r][ccol]);
                    a[mt][1] = *reinterpret_cast<const unsigned*>(&Asp[r + 8][ccol]);
                    a[mt][2] = *reinterpret_cast<const unsigned*>(&Asp[r][ccol + 8]);
                    a[mt][3] = *reinterpret_cast<const unsigned*>(&Asp[r + 8][ccol + 8]);
                }
#pragma unroll
                for (int nt = 0; nt < 6; nt++) {
                    int n = warpN * 48 + nt * 8 + (lane >> 2);
                    unsigned b0 = *reinterpret_cast<const unsigned*>(&Bsp[n][ccol]);
                    unsigned b1 = *reinterpret_cast<const unsigned*>(&Bsp[n][ccol + 8]);
                    mma_bf16(acc[0][nt], a[0], b0, b1);
                    mma_bf16(acc[1][nt], a[1], b0, b1);
                }
            }
        }
        __syncthreads();
    }

    float* outp = g_part + (size_t)blockIdx.y * BT * PCOLS;
#pragma unroll
    for (int mt = 0; mt < 2; mt++)
#pragma unroll
        for (int nt = 0; nt < 6; nt++) {
            int r = row0 + warpM * 32 + mt * 16 + (lane >> 2);
            int c = warpN * 48 + nt * 8 + (lane & 3) * 2;
            float2 v0 = {acc[mt][nt][0], acc[mt][nt][1]};
            float2 v1 = {acc[mt][nt][2], acc[mt][nt][3]};
            *reinterpret_cast<float2*>(&outp[(size_t)r * PCOLS + c]) = v0;
            *reinterpret_cast<float2*>(&outp[(size_t)(r + 8) * PCOLS + c]) = v1;
        }
}

// ---------------- kernel 1b: reduce split-K partials (float4) --------------
__global__ __launch_bounds__(256) void reduce_proj() {
    int i = blockIdx.x * 256 + threadIdx.x;     // float4 index
    if (i < BT * PCOLS / 4) {
        float4 s = {0.f, 0.f, 0.f, 0.f};
#pragma unroll
        for (int k = 0; k < KSPLIT; k++) {
            float4 v = reinterpret_cast<const float4*>(g_part)[(size_t)k * (BT * PCOLS / 4) + i];
            s.x += v.x; s.y += v.y; s.z += v.z; s.w += v.w;
        }
        reinterpret_cast<float4*>(g_proj)[i] = s;
    }
}

// ---------------- kernel 2: dt GEMM via tensor cores (resident smem) -------
__global__ __launch_bounds__(256) void dt_mma(const float* __restrict__ W2,
                                              const float* __restrict__ bdt) {
    __shared__ __nv_bfloat16 Ahi[128][72];
    __shared__ __nv_bfloat16 Alo[128][72];
    __shared__ __nv_bfloat16 Bhi[128][72];
    __shared__ __nv_bfloat16 Blo[128][72];
    const int tid = threadIdx.x;
    const int lane = tid & 31, wid = tid >> 5;
    const int warpM = wid & 3;              // 4 x 32 rows
    const int warpN = wid >> 2;             // 2 x 64 cols
    const int row0 = blockIdx.x * 128;
    const int col0 = blockIdx.y * 128;

#pragma unroll
    for (int i = 0; i < 8; i++) {
        int lin = tid + i * 256;                // 2048 float4
        int r = lin >> 4, q = lin & 15;
        float4 v = *reinterpret_cast<const float4*>(
            g_proj + (size_t)(row0 + r) * PCOLS + 32 + q * 4);
        uint2 hw, lw;
        split4(v, hw, lw);
        *reinterpret_cast<uint2*>(&Ahi[r][q * 4]) = hw;
        *reinterpret_cast<uint2*>(&Alo[r][q * 4]) = lw;
    }
#pragma unroll
    for (int i = 0; i < 8; i++) {
        int lin = tid + i * 256;
        int n = lin >> 4, q = lin & 15;
        float4 v = *reinterpret_cast<const float4*>(
            W2 + (size_t)(col0 + n) * RK + q * 4);
        uint2 hw, lw;
        split4(v, hw, lw);
        *reinterpret_cast<uint2*>(&Bhi[n][q * 4]) = hw;
        *reinterpret_cast<uint2*>(&Blo[n][q * 4]) = lw;
    }
    __syncthreads();

    float acc[2][8][4];
#pragma unroll
    for (int mt = 0; mt < 2; mt++)
#pragma unroll
        for (int nt = 0; nt < 8; nt++)
#pragma unroll
            for (int q = 0; q < 4; q++) acc[mt][nt][q] = 0.0f;

#pragma unroll
    for (int seg = 0; seg < 3; seg++) {
        const __nv_bfloat16 (*Asp)[72] = (seg < 2) ? Ahi : Alo;
        const __nv_bfloat16 (*Bsp)[72] = (seg == 1) ? Blo : Bhi;
#pragma unroll
        for (int k16 = 0; k16 < 64; k16 += 16) {
            const int ccol = k16 + (lane & 3) * 2;
            unsigned a[2][4];
#pragma unroll
            for (int mt = 0; mt < 2; mt++) {
                int r = warpM * 32 + mt * 16 + (lane >> 2);
                a[mt][0] = *reinterpret_cast<const unsigned*>(&Asp[r][ccol]);
                a[mt][1] = *reinterpret_cast<const unsigned*>(&Asp[r + 8][ccol]);
                a[mt][2] = *reinterpret_cast<const unsigned*>(&Asp[r][ccol + 8]);
                a[mt][3] = *reinterpret_cast<const unsigned*>(&Asp[r + 8][ccol + 8]);
            }
#pragma unroll
            for (int nt = 0; nt < 8; nt++) {
                int n = warpN * 64 + nt * 8 + (lane >> 2);
                unsigned b0 = *reinterpret_cast<const unsigned*>(&Bsp[n][ccol]);
                unsigned b1 = *reinterpret_cast<const unsigned*>(&Bsp[n][ccol + 8]);
                mma_bf16(acc[0][nt], a[0], b0, b1);
                mma_bf16(acc[1][nt], a[1], b0, b1);
            }
        }
    }

#pragma unroll
    for (int mt = 0; mt < 2; mt++)
#pragma unroll
        for (int nt = 0; nt < 8; nt++) {
            int r = row0 + warpM * 32 + mt * 16 + (lane >> 2);
            int c = col0 + warpN * 64 + nt * 8 + (lane & 3) * 2;
            float b0 = bdt[c], b1 = bdt[c + 1];
            float v0 = acc[mt][nt][0] + b0;
            float v1 = acc[mt][nt][1] + b1;
            float v2 = acc[mt][nt][2] + b0;
            float v3 = acc[mt][nt][3] + b1;
            float2 r0 = {(v0 > 20.0f) ? v0 : log1pf(__expf(v0)),
                         (v1 > 20.0f) ? v1 : log1pf(__expf(v1))};
            float2 r1 = {(v2 > 20.0f) ? v2 : log1pf(__expf(v2)),
                         (v3 > 20.0f) ? v3 : log1pf(__expf(v3))};
            *reinterpret_cast<float2*>(&g_dt[(size_t)r * DD + c]) = r0;
            *reinterpret_cast<float2*>(&g_dt[(size_t)(r + 8) * DD + c]) = r1;
        }
}

// ---------------- kernel 3: pass 1 — per-chunk local scan (CH=32) ----------
__global__ __launch_bounds__(256, 6) void scan_pass1(const float* __restrict__ x,
                                                     const float* __restrict__ logA) {
    __shared__ float sdt[CH][128];
    __shared__ float sx[CH][128];
    __shared__ float Bv[CH * NST];
    const int tid = threadIdx.x;
    const int dloc = tid >> 1;
    const int d0 = blockIdx.x * 128;
    const int nb = (tid & 1) * 8;
    const int c = blockIdx.y;
    const int b = blockIdx.z;

    const size_t rowbase = (size_t)(b * TT + c * CH) * DD + d0;
#pragma unroll
    for (int i = 0; i < 4; i++) {
        int lin = tid + i * 256;                // 1024 float4
        int t = lin >> 5, q = lin & 31;
        *reinterpret_cast<float4*>(&sdt[t][q * 4]) =
            *reinterpret_cast<const float4*>(g_dt + rowbase + (size_t)t * DD + q * 4);
        *reinterpret_cast<float4*>(&sx[t][q * 4]) =
            *reinterpret_cast<const float4*>(x + rowbase + (size_t)t * DD + q * 4);
    }
#pragma unroll
    for (int i = 0; i < 2; i++) {               // CH*NST = 512 Bv entries
        int lin = tid + i * 256;
        int t = lin >> 4, n = lin & 15;
        float A = -ex2(logA[n] * LOG2E);
        Bv[lin] = g_proj[(size_t)(b * TT + c * CH + t) * PCOLS + n] * rcpa(A + 1e-8f);
    }

    float An2[8], h[8];
#pragma unroll
    for (int j = 0; j < 8; j++) {
        An2[j] = -ex2(logA[nb + j] * LOG2E) * LOG2E;
        h[j] = 0.0f;
    }
    __syncthreads();

    float sumdt = 0.0f;
#pragma unroll
    for (int t = 0; t < CH; t++) {
        float dtv = sdt[t][dloc];
        float xv = sx[t][dloc];
        sumdt += dtv;
        float4 b0 = *reinterpret_cast<const float4*>(&Bv[t * NST + nb]);
        float4 b1 = *reinterpret_cast<const float4*>(&Bv[t * NST + nb + 4]);
        float bv[8] = {b0.x, b0.y, b0.z, b0.w, b1.x, b1.y, b1.z, b1.w};
#pragma unroll
        for (int j = 0; j < 8; j++) {
            float a = ex2(dtv * An2[j]);
            float g = xv * bv[j];
            h[j] = fmaf(a, h[j] + g, -g);
        }
    }

    const int d = d0 + dloc;
    size_t base = (((size_t)b * NC + c) * DD + d) * NST + nb;
    float4 H0 = {h[0], h[1], h[2], h[3]};
    float4 H1 = {h[4], h[5], h[6], h[7]};
    *reinterpret_cast<float4*>(g_H + base)     = H0;
    *reinterpret_cast<float4*>(g_H + base + 4) = H1;
    if ((tid & 1) == 0) g_S[((size_t)b * NC + c) * DD + d] = sumdt;
}

// ---------------- kernel 4: combine chunks (P computed on the fly) ---------
__global__ __launch_bounds__(256) void combine(const float* __restrict__ logA) {
    int idx = blockIdx.x * 256 + threadIdx.x;     // b*DD*NST + d*NST + n
    int b = idx / (DD * NST);
    int rem = idx - b * (DD * NST);
    int d = rem >> 4, n = rem & 15;
    float An2 = -ex2(logA[n] * LOG2E) * LOG2E;
    float run = 0.0f;
#pragma unroll 8
    for (int c = 0; c < NC; c++) {
        float sumdt = g_S[((size_t)b * NC + c) * DD + d];
        size_t off = ((size_t)b * NC + c) * (DD * NST) + rem;
        float H = g_H[off];
        float P = ex2(An2 * sumdt);
        float nw = fmaf(P, run, H);
        g_H[off] = run;      // becomes the chunk's initial state
        run = nw;
    }
}

// ---------------- kernel 5: pass 2 — re-scan with correct init, emit y -----
// sy is ALIASED onto sdt: sdt[t][dloc] is read by the owning lane pair
// strictly before the nh==0 lane writes sy[t][dloc] (same warp, program
// order), and no other thread touches that column during the loop.
__global__ __launch_bounds__(256, 5) void scan_pass2(const float* __restrict__ x,
                                                     const float* __restrict__ logA,
                                                     const float* __restrict__ Dskip,
                                                     float* __restrict__ out) {
    __shared__ float sdt[CH][128];
    __shared__ float sx[CH][128];
    __shared__ float Bv[CH * NST];
    __shared__ float Cs[CH * NST];
    float (*sy)[128] = sdt;                  // alias (see note above)
    const int tid = threadIdx.x;
    const int dloc = tid >> 1;
    const int d0 = blockIdx.x * 128;
    const int nh = tid & 1;
    const int nb = nh * 8;
    const int c = blockIdx.y;
    const int b = blockIdx.z;

    const size_t rowbase = (size_t)(b * TT + c * CH) * DD + d0;
#pragma unroll
    for (int i = 0; i < 4; i++) {
        int lin = tid + i * 256;
        int t = lin >> 5, q = lin & 31;
        *reinterpret_cast<float4*>(&sdt[t][q * 4]) =
            *reinterpret_cast<const float4*>(g_dt + rowbase + (size_t)t * DD + q * 4);
        *reinterpret_cast<float4*>(&sx[t][q * 4]) =
            *reinterpret_cast<const float4*>(x + rowbase + (size_t)t * DD + q * 4);
    }
#pragma unroll
    for (int i = 0; i < 2; i++) {
        int lin = tid + i * 256;
        int t = lin >> 4, n = lin & 15;
        float A = -ex2(logA[n] * LOG2E);
        size_t prow = (size_t)(b * TT + c * CH + t) * PCOLS;
        Bv[lin] = g_proj[prow + n] * rcpa(A + 1e-8f);
        Cs[lin] = g_proj[prow + 16 + n];
    }

    const int d = d0 + dloc;
    float An2[8], h[8];
    size_t base = (((size_t)b * NC + c) * DD + d) * NST + nb;
    float4 H0 = *reinterpret_cast<const float4*>(g_H + base);
    float4 H1 = *reinterpret_cast<const float4*>(g_H + base + 4);
    h[0] = H0.x; h[1] = H0.y; h[2] = H0.z; h[3] = H0.w;
    h[4] = H1.x; h[5] = H1.y; h[6] = H1.z; h[7] = H1.w;
#pragma unroll
    for (int j = 0; j < 8; j++)
        An2[j] = -ex2(logA[nb + j] * LOG2E) * LOG2E;
    const float dsk = Dskip[d];
    __syncthreads();

#pragma unroll
    for (int t = 0; t < CH; t++) {
        float dtv = sdt[t][dloc];
        float xv = sx[t][dloc];
        float4 b0 = *reinterpret_cast<const float4*>(&Bv[t * NST + nb]);
        float4 b1 = *reinterpret_cast<const float4*>(&Bv[t * NST + nb + 4]);
        float bv[8] = {b0.x, b0.y, b0.z, b0.w, b1.x, b1.y, b1.z, b1.w};
        float4 c0 = *reinterpret_cast<const float4*>(&Cs[t * NST + nb]);
        float4 c1 = *reinterpret_cast<const float4*>(&Cs[t * NST + nb + 4]);
        float cv[8] = {c0.x, c0.y, c0.z, c0.w, c1.x, c1.y, c1.z, c1.w};
        float y = 0.0f;
#pragma unroll
        for (int j = 0; j < 8; j++) {
            float a = ex2(dtv * An2[j]);
            float g = xv * bv[j];
            h[j] = fmaf(a, h[j] + g, -g);
            y = fmaf(h[j], cv[j], y);
        }
        y += __shfl_xor_sync(0xffffffffu, y, 1);
        if (nh == 0) sy[t][dloc] = fmaf(dsk, xv, y);
    }
    __syncthreads();

#pragma unroll
    for (int i = 0; i < 4; i++) {
        int lin = tid + i * 256;
        int t = lin >> 5, q = lin & 31;
        *reinterpret_cast<float4*>(out + rowbase + (size_t)t * DD + q * 4) =
            *reinterpret_cast<const float4*>(&sy[t][q * 4]);
    }
}

// ---------------- launcher -------------------------------------------------
extern "C" void kernel_launch(void* const* d_in, const int* in_sizes, int n_in,
                              void* d_out, int out_size) {
    const float* x    = (const float*)d_in[0];
    const float* WB   = (const float*)d_in[1];
    const float* WC   = (const float*)d_in[2];
    const float* Wdt1 = (const float*)d_in[3];
    const float* Wdt2 = (const float*)d_in[4];
    const float* bdt2 = (const float*)d_in[5];
    const float* logA = (const float*)d_in[6];
    const float* Dsk  = (const float*)d_in[7];
    float* out = (float*)d_out;

    proj_mma<<<dim3(BT / 128, KSPLIT), 256>>>(x, WB, WC, Wdt1);
    reduce_proj<<<(BT * PCOLS / 4 + 255) / 256, 256>>>();
    dt_mma<<<dim3(BT / 128, DD / 128), 256>>>(Wdt2, bdt2);
    scan_pass1<<<dim3(DD / 128, NC, BSZ), 256>>>(x, logA);
    combine<<<(BSZ * DD * NST) / 256, 256>>>(logA);
    scan_pass2<<<dim3(DD / 128, NC, BSZ), 256>>>(x, logA, Dsk, out);
}

// round 15
// speedup vs baseline: 1.8280x; 1.0077x over previous
#include <cuda_runtime.h>
#include <cuda_bf16.h>
#include <math.h>

#define BSZ 2
#define TT 2048
#define DD 1024
#define NST 16
#define RK 64
#define BT (BSZ*TT)          // 4096
#define NC 64                // chunks
#define CH (TT/NC)           // 32 steps per chunk
#define PCOLS 96             // 16 B + 16 C + 64 R
#define KSPLIT 4
#define LOG2E 1.44269504f

__device__ __forceinline__ float ex2(float v) {
    float r; asm("ex2.approx.f32 %0, %1;" : "=f"(r) : "f"(v)); return r;
}
__device__ __forceinline__ float rcpa(float v) {
    float r; asm("rcp.approx.f32 %0, %1;" : "=f"(r) : "f"(v)); return r;
}

// ---------------- scratch (static device memory; no allocs allowed) --------
__device__ float g_part[KSPLIT * BT * PCOLS]; // split-K partials
__device__ float g_bc[BT * 32];               // compact B(0-15),C(16-31) per row
__device__ __nv_bfloat16 g_rhi[BT * RK];      // bf16 hi of R (proj cols 32-95)
__device__ __nv_bfloat16 g_rlo[BT * RK];      // bf16 lo of R
__device__ float g_dt[BT * DD];               // softplus(dt_raw)
__device__ float g_S[BSZ * NC * DD];          // per-chunk sum of dt
__device__ float g_H[BSZ * NC * DD * NST];    // chunk-local final h -> becomes init h

// split one float4 into two packed bf16x4 (hi, lo)
__device__ __forceinline__ void split4(float4 v, uint2& hw, uint2& lw) {
    float f[4] = {v.x, v.y, v.z, v.w};
    unsigned h[2], l[2];
#pragma unroll
    for (int k = 0; k < 2; k++) {
        __nv_bfloat16 h0 = __float2bfloat16(f[2 * k]);
        __nv_bfloat16 h1 = __float2bfloat16(f[2 * k + 1]);
        __nv_bfloat16 l0 = __float2bfloat16(f[2 * k] - __bfloat162float(h0));
        __nv_bfloat16 l1 = __float2bfloat16(f[2 * k + 1] - __bfloat162float(h1));
        h[k] = (unsigned)__bfloat16_as_ushort(h0) | ((unsigned)__bfloat16_as_ushort(h1) << 16);
        l[k] = (unsigned)__bfloat16_as_ushort(l0) | ((unsigned)__bfloat16_as_ushort(l1) << 16);
    }
    hw = make_uint2(h[0], h[1]);
    lw = make_uint2(l[0], l[1]);
}

__device__ __forceinline__ void mma_bf16(float* d, const unsigned* a,
                                         unsigned b0, unsigned b1) {
    asm("mma.sync.aligned.m16n8k16.row.col.f32.bf16.bf16.f32 "
        "{%0,%1,%2,%3}, {%4,%5,%6,%7}, {%8,%9}, {%0,%1,%2,%3};"
        : "+f"(d[0]), "+f"(d[1]), "+f"(d[2]), "+f"(d[3])
        : "r"(a[0]), "r"(a[1]), "r"(a[2]), "r"(a[3]), "r"(b0), "r"(b1));
}

// ---------------- kernel 1: proj GEMM via tensor cores ---------------------
// grid (BT/128, KSPLIT=4), block 256. 256 K per block (8 k-tiles of 32).
__global__ __launch_bounds__(256) void proj_mma(const float* __restrict__ x,
                                                const float* __restrict__ WB,
                                                const float* __restrict__ WC,
                                                const float* __restrict__ Wdt1) {
    __shared__ __nv_bfloat16 Ahi[128][40];
    __shared__ __nv_bfloat16 Alo[128][40];
    __shared__ __nv_bfloat16 Bhi[96][40];
    __shared__ __nv_bfloat16 Blo[96][40];
    const int tid = threadIdx.x;
    const int lane = tid & 31, wid = tid >> 5;
    const int warpM = wid & 3;              // 4 x 32 rows
    const int warpN = wid >> 2;             // 2 x 48 cols
    const int row0 = blockIdx.x * 128;
    const int kb = blockIdx.y * (DD / KSPLIT);   // 256 K columns per block

    float4 xr[4];
    float4 wr[3];
    const int bq = tid & 7;

    auto ldg_tile = [&](int kcur) {
#pragma unroll
        for (int i = 0; i < 4; i++) {
            int lin = tid + i * 256;
            int r = lin >> 3, q = lin & 7;
            xr[i] = *reinterpret_cast<const float4*>(
                x + (size_t)(row0 + r) * DD + kcur + q * 4);
        }
#pragma unroll
        for (int i = 0; i < 3; i++) {
            int lin = tid + i * 256;
            if (lin < 768) {
                int n = lin >> 3;
                const float* src = (n < 16) ? (WB + (size_t)n * DD)
                                  : (n < 32) ? (WC + (size_t)(n - 16) * DD)
                                             : (Wdt1 + (size_t)(n - 32) * DD);
                wr[i] = *reinterpret_cast<const float4*>(src + kcur + bq * 4);
            }
        }
    };
    auto sts_tile = [&]() {
#pragma unroll
        for (int i = 0; i < 4; i++) {
            int lin = tid + i * 256;
            int r = lin >> 3, q = lin & 7;
            uint2 hw, lw;
            split4(xr[i], hw, lw);
            *reinterpret_cast<uint2*>(&Ahi[r][q * 4]) = hw;
            *reinterpret_cast<uint2*>(&Alo[r][q * 4]) = lw;
        }
#pragma unroll
        for (int i = 0; i < 3; i++) {
            int lin = tid + i * 256;
            if (lin < 768) {
                int n = lin >> 3;
                uint2 hw, lw;
                split4(wr[i], hw, lw);
                *reinterpret_cast<uint2*>(&Bhi[n][bq * 4]) = hw;
                *reinterpret_cast<uint2*>(&Blo[n][bq * 4]) = lw;
            }
        }
    };

    float acc[2][6][4];
#pragma unroll
    for (int mt = 0; mt < 2; mt++)
#pragma unroll
        for (int nt = 0; nt < 6; nt++)
#pragma unroll
            for (int q = 0; q < 4; q++) acc[mt][nt][q] = 0.0f;

    ldg_tile(kb);
#pragma unroll 1
    for (int kt = 0; kt < 8; kt++) {
        sts_tile();
        __syncthreads();
        if (kt < 7) ldg_tile(kb + (kt + 1) * 32);   // overlaps MMA below

#pragma unroll
        for (int seg = 0; seg < 3; seg++) {
            const __nv_bfloat16 (*Asp)[40] = (seg < 2) ? Ahi : Alo;
            const __nv_bfloat16 (*Bsp)[40] = (seg == 1) ? Blo : Bhi;
#pragma unroll
            for (int k16 = 0; k16 < 32; k16 += 16) {
                const int ccol = k16 + (lane & 3) * 2;
                unsigned a[2][4];
#pragma unroll
                for (int mt = 0; mt < 2; mt++) {
                    int r = warpM * 32 + mt * 16 + (lane >> 2);
                    a[mt][0] = *reinterpret_cast<const unsigned*>(&Asp[r][ccol]);
                    a[mt][1] = *reinterpret_cast<const unsigned*>(&Asp[r + 8][ccol]);
                    a[mt][2] = *reinterpret_cast<const unsigned*>(&Asp[r][ccol + 8]);
                    a[mt][3] = *reinterpret_cast<const unsigned*>(&Asp[r + 8][ccol + 8]);
                }
#pragma unroll
                for (int nt = 0; nt < 6; nt++) {
                    int n = warpN * 48 + nt * 8 + (lane >> 2);
                    unsigned b0 = *reinterpret_cast<const unsigned*>(&Bsp[n][ccol]);
                    unsigned b1 = *reinterpret_cast<const unsigned*>(&Bsp[n][ccol + 8]);
                    mma_bf16(acc[0][nt], a[0], b0, b1);
                    mma_bf16(acc[1][nt], a[1], b0, b1);
                }
            }
        }
        __syncthreads();
    }

    float* outp = g_part + (size_t)blockIdx.y * BT * PCOLS;
#pragma unroll
    for (int mt = 0; mt < 2; mt++)
#pragma unroll
        for (int nt = 0; nt < 6; nt++) {
            int r = row0 + warpM * 32 + mt * 16 + (lane >> 2);
            int c = warpN * 48 + nt * 8 + (lane & 3) * 2;
            float2 v0 = {acc[mt][nt][0], acc[mt][nt][1]};
            float2 v1 = {acc[mt][nt][2], acc[mt][nt][3]};
            *reinterpret_cast<float2*>(&outp[(size_t)r * PCOLS + c]) = v0;
            *reinterpret_cast<float2*>(&outp[(size_t)(r + 8) * PCOLS + c]) = v1;
        }
}

// ---------------- kernel 1b: reduce partials -> compact g_bc + bf16 R ------
__global__ __launch_bounds__(256) void reduce_proj() {
    int i = blockIdx.x * 256 + threadIdx.x;     // float4 index into [row][96]
    if (i < BT * PCOLS / 4) {
        float4 s = {0.f, 0.f, 0.f, 0.f};
#pragma unroll
        for (int k = 0; k < KSPLIT; k++) {
            float4 v = reinterpret_cast<const float4*>(g_part)[(size_t)k * (BT * PCOLS / 4) + i];
            s.x += v.x; s.y += v.y; s.z += v.z; s.w += v.w;
        }
        int row = i / (PCOLS / 4);
        int col4 = i - row * (PCOLS / 4);       // 0..23
        if (col4 < 8) {                         // B,C columns -> compact fp32
            reinterpret_cast<float4*>(g_bc)[row * 8 + col4] = s;
        } else {                                // R columns -> bf16 hi/lo
            int rq = col4 - 8;                  // 0..15
            uint2 hw, lw;
            split4(s, hw, lw);
            reinterpret_cast<uint2*>(g_rhi)[(size_t)row * (RK / 4) + rq] = hw;
            reinterpret_cast<uint2*>(g_rlo)[(size_t)row * (RK / 4) + rq] = lw;
        }
    }
}

// ---------------- kernel 2: dt GEMM via tensor cores (resident smem) -------
__global__ __launch_bounds__(256) void dt_mma(const float* __restrict__ W2,
                                              const float* __restrict__ bdt) {
    __shared__ __nv_bfloat16 Ahi[128][72];
    __shared__ __nv_bfloat16 Alo[128][72];
    __shared__ __nv_bfloat16 Bhi[128][72];
    __shared__ __nv_bfloat16 Blo[128][72];
    const int tid = threadIdx.x;
    const int lane = tid & 31, wid = tid >> 5;
    const int warpM = wid & 3;              // 4 x 32 rows
    const int warpN = wid >> 2;             // 2 x 64 cols
    const int row0 = blockIdx.x * 128;
    const int col0 = blockIdx.y * 128;

    // stage A: pre-split bf16 R (direct uint2 copies)
#pragma unroll
    for (int i = 0; i < 8; i++) {
        int lin = tid + i * 256;                // 2048 uint2
        int r = lin >> 4, q = lin & 15;
        *reinterpret_cast<uint2*>(&Ahi[r][q * 4]) =
            reinterpret_cast<const uint2*>(g_rhi)[(size_t)(row0 + r) * (RK / 4) + q];
        *reinterpret_cast<uint2*>(&Alo[r][q * 4]) =
            reinterpret_cast<const uint2*>(g_rlo)[(size_t)(row0 + r) * (RK / 4) + q];
    }
    // stage B = W2 rows col0..col0+127, 128x64, split hi/lo
#pragma unroll
    for (int i = 0; i < 8; i++) {
        int lin = tid + i * 256;
        int n = lin >> 4, q = lin & 15;
        float4 v = *reinterpret_cast<const float4*>(
            W2 + (size_t)(col0 + n) * RK + q * 4);
        uint2 hw, lw;
        split4(v, hw, lw);
        *reinterpret_cast<uint2*>(&Bhi[n][q * 4]) = hw;
        *reinterpret_cast<uint2*>(&Blo[n][q * 4]) = lw;
    }
    __syncthreads();

    float acc[2][8][4];
#pragma unroll
    for (int mt = 0; mt < 2; mt++)
#pragma unroll
        for (int nt = 0; nt < 8; nt++)
#pragma unroll
            for (int q = 0; q < 4; q++) acc[mt][nt][q] = 0.0f;

#pragma unroll
    for (int seg = 0; seg < 3; seg++) {
        const __nv_bfloat16 (*Asp)[72] = (seg < 2) ? Ahi : Alo;
        const __nv_bfloat16 (*Bsp)[72] = (seg == 1) ? Blo : Bhi;
#pragma unroll
        for (int k16 = 0; k16 < 64; k16 += 16) {
            const int ccol = k16 + (lane & 3) * 2;
            unsigned a[2][4];
#pragma unroll
            for (int mt = 0; mt < 2; mt++) {
                int r = warpM * 32 + mt * 16 + (lane >> 2);
                a[mt][0] = *reinterpret_cast<const unsigned*>(&Asp[r][ccol]);
                a[mt][1] = *reinterpret_cast<const unsigned*>(&Asp[r + 8][ccol]);
                a[mt][2] = *reinterpret_cast<const unsigned*>(&Asp[r][ccol + 8]);
                a[mt][3] = *reinterpret_cast<const unsigned*>(&Asp[r + 8][ccol + 8]);
            }
#pragma unroll
            for (int nt = 0; nt < 8; nt++) {
                int n = warpN * 64 + nt * 8 + (lane >> 2);
                unsigned b0 = *reinterpret_cast<const unsigned*>(&Bsp[n][ccol]);
                unsigned b1 = *reinterpret_cast<const unsigned*>(&Bsp[n][ccol + 8]);
                mma_bf16(acc[0][nt], a[0], b0, b1);
                mma_bf16(acc[1][nt], a[1], b0, b1);
            }
        }
    }

#pragma unroll
    for (int mt = 0; mt < 2; mt++)
#pragma unroll
        for (int nt = 0; nt < 8; nt++) {
            int r = row0 + warpM * 32 + mt * 16 + (lane >> 2);
            int c = col0 + warpN * 64 + nt * 8 + (lane & 3) * 2;
            float b0 = bdt[c], b1 = bdt[c + 1];
            float v0 = acc[mt][nt][0] + b0;
            float v1 = acc[mt][nt][1] + b1;
            float v2 = acc[mt][nt][2] + b0;
            float v3 = acc[mt][nt][3] + b1;
            float2 r0 = {(v0 > 20.0f) ? v0 : log1pf(__expf(v0)),
                         (v1 > 20.0f) ? v1 : log1pf(__expf(v1))};
            float2 r1 = {(v2 > 20.0f) ? v2 : log1pf(__expf(v2)),
                         (v3 > 20.0f) ? v3 : log1pf(__expf(v3))};
            *reinterpret_cast<float2*>(&g_dt[(size_t)r * DD + c]) = r0;
            *reinterpret_cast<float2*>(&g_dt[(size_t)(r + 8) * DD + c]) = r1;
        }
}

// ---------------- kernel 3: pass 1 — per-chunk local scan (CH=32) ----------
__global__ __launch_bounds__(256, 6) void scan_pass1(const float* __restrict__ x,
                                                     const float* __restrict__ logA) {
    __shared__ float sdt[CH][128];
    __shared__ float sx[CH][128];
    __shared__ float Bv[CH * NST];
    const int tid = threadIdx.x;
    const int dloc = tid >> 1;
    const int d0 = blockIdx.x * 128;
    const int nb = (tid & 1) * 8;
    const int c = blockIdx.y;
    const int b = blockIdx.z;

    const size_t rowbase = (size_t)(b * TT + c * CH) * DD + d0;
#pragma unroll
    for (int i = 0; i < 4; i++) {
        int lin = tid + i * 256;                // 1024 float4
        int t = lin >> 5, q = lin & 31;
        *reinterpret_cast<float4*>(&sdt[t][q * 4]) =
            *reinterpret_cast<const float4*>(g_dt + rowbase + (size_t)t * DD + q * 4);
        *reinterpret_cast<float4*>(&sx[t][q * 4]) =
            *reinterpret_cast<const float4*>(x + rowbase + (size_t)t * DD + q * 4);
    }
#pragma unroll
    for (int i = 0; i < 2; i++) {               // CH*NST = 512 Bv entries
        int lin = tid + i * 256;
        int t = lin >> 4, n = lin & 15;
        float A = -ex2(logA[n] * LOG2E);
        Bv[lin] = g_bc[(size_t)(b * TT + c * CH + t) * 32 + n] * rcpa(A + 1e-8f);
    }

    float An2[8], h[8];
#pragma unroll
    for (int j = 0; j < 8; j++) {
        An2[j] = -ex2(logA[nb + j] * LOG2E) * LOG2E;
        h[j] = 0.0f;
    }
    __syncthreads();

    float sumdt = 0.0f;
#pragma unroll
    for (int t = 0; t < CH; t++) {
        float dtv = sdt[t][dloc];
        float xv = sx[t][dloc];
        sumdt += dtv;
        float4 b0 = *reinterpret_cast<const float4*>(&Bv[t * NST + nb]);
        float4 b1 = *reinterpret_cast<const float4*>(&Bv[t * NST + nb + 4]);
        float bv[8] = {b0.x, b0.y, b0.z, b0.w, b1.x, b1.y, b1.z, b1.w};
#pragma unroll
        for (int j = 0; j < 8; j++) {
            float a = ex2(dtv * An2[j]);
            float g = xv * bv[j];
            h[j] = fmaf(a, h[j] + g, -g);
        }
    }

    const int d = d0 + dloc;
    size_t base = (((size_t)b * NC + c) * DD + d) * NST + nb;
    float4 H0 = {h[0], h[1], h[2], h[3]};
    float4 H1 = {h[4], h[5], h[6], h[7]};
    *reinterpret_cast<float4*>(g_H + base)     = H0;
    *reinterpret_cast<float4*>(g_H + base + 4) = H1;
    if ((tid & 1) == 0) g_S[((size_t)b * NC + c) * DD + d] = sumdt;
}

// ---------------- kernel 4: combine chunks (P computed on the fly) ---------
__global__ __launch_bounds__(256) void combine(const float* __restrict__ logA) {
    int idx = blockIdx.x * 256 + threadIdx.x;     // b*DD*NST + d*NST + n
    int b = idx / (DD * NST);
    int rem = idx - b * (DD * NST);
    int d = rem >> 4, n = rem & 15;
    float An2 = -ex2(logA[n] * LOG2E) * LOG2E;
    float run = 0.0f;
#pragma unroll 8
    for (int c = 0; c < NC; c++) {
        float sumdt = g_S[((size_t)b * NC + c) * DD + d];
        size_t off = ((size_t)b * NC + c) * (DD * NST) + rem;
        float H = g_H[off];
        float P = ex2(An2 * sumdt);
        float nw = fmaf(P, run, H);
        g_H[off] = run;      // becomes the chunk's initial state
        run = nw;
    }
}

// ---------------- kernel 5: pass 2 — re-scan with correct init, emit y -----
// sy is ALIASED onto sdt: sdt[t][dloc] is read by the owning lane pair
// strictly before the nh==0 lane writes sy[t][dloc] (same warp, program
// order), and no other thread touches that column during the loop.
__global__ __launch_bounds__(256, 5) void scan_pass2(const float* __restrict__ x,
                                                     const float* __restrict__ logA,
                                                     const float* __restrict__ Dskip,
                                                     float* __restrict__ out) {
    __shared__ float sdt[CH][128];
    __shared__ float sx[CH][128];
    __shared__ float Bv[CH * NST];
    __shared__ float Cs[CH * NST];
    float (*sy)[128] = sdt;                  // alias (see note above)
    const int tid = threadIdx.x;
    const int dloc = tid >> 1;
    const int d0 = blockIdx.x * 128;
    const int nh = tid & 1;
    const int nb = nh * 8;
    const int c = blockIdx.y;
    const int b = blockIdx.z;

    const size_t rowbase = (size_t)(b * TT + c * CH) * DD + d0;
#pragma unroll
    for (int i = 0; i < 4; i++) {
        int lin = tid + i * 256;
        int t = lin >> 5, q = lin & 31;
        *reinterpret_cast<float4*>(&sdt[t][q * 4]) =
            *reinterpret_cast<const float4*>(g_dt + rowbase + (size_t)t * DD + q * 4);
        *reinterpret_cast<float4*>(&sx[t][q * 4]) =
            *reinterpret_cast<const float4*>(x + rowbase + (size_t)t * DD + q * 4);
    }
#pragma unroll
    for (int i = 0; i < 2; i++) {
        int lin = tid + i * 256;
        int t = lin >> 4, n = lin & 15;
        float A = -ex2(logA[n] * LOG2E);
        size_t prow = (size_t)(b * TT + c * CH + t) * 32;
        Bv[lin] = g_bc[prow + n] * rcpa(A + 1e-8f);
        Cs[lin] = g_bc[prow + 16 + n];
    }

    const int d = d0 + dloc;
    float An2[8], h[8];
    size_t base = (((size_t)b * NC + c) * DD + d) * NST + nb;
    float4 H0 = *reinterpret_cast<const float4*>(g_H + base);
    float4 H1 = *reinterpret_cast<const float4*>(g_H + base + 4);
    h[0] = H0.x; h[1] = H0.y; h[2] = H0.z; h[3] = H0.w;
    h[4] = H1.x; h[5] = H1.y; h[6] = H1.z; h[7] = H1.w;
#pragma unroll
    for (int j = 0; j < 8; j++)
        An2[j] = -ex2(logA[nb + j] * LOG2E) * LOG2E;
    const float dsk = Dskip[d];
    __syncthreads();

#pragma unroll
    for (int t = 0; t < CH; t++) {
        float dtv = sdt[t][dloc];
        float xv = sx[t][dloc];
        float4 b0 = *reinterpret_cast<const float4*>(&Bv[t * NST + nb]);
        float4 b1 = *reinterpret_cast<const float4*>(&Bv[t * NST + nb + 4]);
        float bv[8] = {b0.x, b0.y, b0.z, b0.w, b1.x, b1.y, b1.z, b1.w};
        float4 c0 = *reinterpret_cast<const float4*>(&Cs[t * NST + nb]);
        float4 c1 = *reinterpret_cast<const float4*>(&Cs[t * NST + nb + 4]);
        float cv[8] = {c0.x, c0.y, c0.z, c0.w, c1.x, c1.y, c1.z, c1.w};
        float y = 0.0f;
#pragma unroll
        for (int j = 0; j < 8; j++) {
            float a = ex2(dtv * An2[j]);
            float g = xv * bv[j];
            h[j] = fmaf(a, h[j] + g, -g);
            y = fmaf(h[j], cv[j], y);
        }
        y += __shfl_xor_sync(0xffffffffu, y, 1);
        if (nh == 0) sy[t][dloc] = fmaf(dsk, xv, y);
    }
    __syncthreads();

#pragma unroll
    for (int i = 0; i < 4; i++) {
        int lin = tid + i * 256;
        int t = lin >> 5, q = lin & 31;
        *reinterpret_cast<float4*>(out + rowbase + (size_t)t * DD + q * 4) =
            *reinterpret_cast<const float4*>(&sy[t][q * 4]);
    }
}

// ---------------- launcher -------------------------------------------------
extern "C" void kernel_launch(void* const* d_in, const int* in_sizes, int n_in,
                              void* d_out, int out_size) {
    const float* x    = (const float*)d_in[0];
    const float* WB   = (const float*)d_in[1];
    const float* WC   = (const float*)d_in[2];
    const float* Wdt1 = (const float*)d_in[3];
    const float* Wdt2 = (const float*)d_in[4];
    const float* bdt2 = (const float*)d_in[5];
    const float* logA = (const float*)d_in[6];
    const float* Dsk  = (const float*)d_in[7];
    float* out = (float*)d_out;

    proj_mma<<<dim3(BT / 128, KSPLIT), 256>>>(x, WB, WC, Wdt1);
    reduce_proj<<<(BT * PCOLS / 4 + 255) / 256, 256>>>();
    dt_mma<<<dim3(BT / 128, DD / 128), 256>>>(Wdt2, bdt2);
    scan_pass1<<<dim3(DD / 128, NC, BSZ), 256>>>(x, logA);
    combine<<<(BSZ * DD * NST) / 256, 256>>>(logA);
    scan_pass2<<<dim3(DD / 128, NC, BSZ), 256>>>(x, logA, Dsk, out);
}